// round 1
// baseline (speedup 1.0000x reference)
#include <cuda_runtime.h>
#include <math.h>

#define NUME     30000
#define NUMR     8
#define DIM_IN   128
#define DIM_OUT  128
#define DIM_R    64
#define DIM_T    32
#define HEADS    4
#define DHEAD    32
#define R_TOTAL  17
#define N_NODES  20000
#define N_EDGES  15000
#define BATCH    1024
#define DIN      160
#define KCLS     (DIM_OUT + DIM_R)   // 192
#define NEG_SLOPE 0.2f

// ---------------- scratch (device globals; no allocation allowed) ----------------
__device__ __align__(16) float    g_x[N_NODES * DIN];                         // node features [h | phi]
__device__ __align__(16) float    g_z[(size_t)R_TOTAL * N_NODES * DIM_OUT];   // per-relation transformed feats
__device__ __align__(16) float    g_el[R_TOTAL * N_NODES * HEADS];
__device__ __align__(16) float    g_er[R_TOTAL * N_NODES * HEADS];
__device__ __align__(16) unsigned g_menc[R_TOTAL * N_NODES * HEADS];          // encoded segment max
__device__ __align__(16) float    g_den[R_TOTAL * N_NODES * HEADS];           // softmax denominator
__device__ __align__(16) float    g_ex[R_TOTAL * N_EDGES * HEADS];            // exp(e-m), then alpha in-place
__device__ __align__(16) float    g_acc[N_NODES * DIM_OUT];                   // sum over relations
__device__ __align__(16) float    g_A[2 * BATCH * KCLS];                      // classifier A matrices

// monotonic float<->uint encoding for atomicMax on signed floats
__device__ __forceinline__ unsigned fenc(float f) {
    unsigned u = __float_as_uint(f);
    return (u & 0x80000000u) ? ~u : (u | 0x80000000u);
}
__device__ __forceinline__ float fdec(unsigned u) {
    return (u & 0x80000000u) ? __uint_as_float(u & 0x7FFFFFFFu) : __uint_as_float(~u);
}

// ---------------- kernels ----------------

__global__ void k_init(const int* __restrict__ node_ids,
                       const float* __restrict__ entity_emb,
                       const float* __restrict__ basis_freq,
                       const float* __restrict__ phase,
                       const int* __restrict__ ts_ptr) {
    long i = (long)blockIdx.x * blockDim.x + threadIdx.x;
    if (i >= (long)N_NODES * DIN) return;
    int n = (int)(i / DIN);
    int c = (int)(i % DIN);
    int nid = node_ids[n];
    if (c < DIM_IN) {
        g_x[i] = entity_emb[(long)(nid % NUME) * DIM_IN + c];
    } else {
        int ts = ts_ptr ? ts_ptr[0] : 31;
        float dt = (float)(ts - 1 - nid / NUME);
        int t = c - DIM_IN;
        g_x[i] = cosf(dt * basis_freq[t] + phase[t]);
    }
}

__global__ void k_zero() {
    long i = (long)blockIdx.x * blockDim.x + threadIdx.x;
    const long NA = (long)R_TOTAL * N_NODES * HEADS;
    const long NB = (long)N_NODES * DIM_OUT;
    if (i < NA) { g_menc[i] = 0u; g_den[i] = 0.0f; }
    if (i < NB) { g_acc[i] = 0.0f; }
}

// C[z] (M x N) = A[z] (M x K, row-major, lda=K) @ B[z] (K x N, row-major, ldb=N) (+ bias)
__global__ __launch_bounds__(256) void sgemm128(
    const float* __restrict__ Aall, long sA,
    const float* __restrict__ Ball, long sB,
    float* __restrict__ Call, long sC,
    const float* __restrict__ bias,
    int M, int N, int K) {
    const float* A = Aall + sA * blockIdx.z;
    const float* B = Ball + sB * blockIdx.z;
    float* C = Call + sC * blockIdx.z;
    int bm = blockIdx.y * 128;
    int bn = blockIdx.x * 128;
    int tid = threadIdx.x;
    int tx = tid & 15, ty = tid >> 4;

    __shared__ float As[8][128];
    __shared__ float Bs[8][128];

    float acc[8][8];
#pragma unroll
    for (int i = 0; i < 8; i++)
#pragma unroll
        for (int j = 0; j < 8; j++) acc[i][j] = 0.0f;

    int arow = bm + (tid >> 1);
    int acol4 = (tid & 1) * 4;
    int brow = tid >> 5;
    int bcol = bn + (tid & 31) * 4;
    bool avalid = (arow < M);
    bool bvalid = (bcol + 3) < N;   // N is a multiple of 4 in all uses

    for (int k0 = 0; k0 < K; k0 += 8) {
        float4 av = make_float4(0.f, 0.f, 0.f, 0.f);
        if (avalid) av = *reinterpret_cast<const float4*>(&A[(long)arow * K + k0 + acol4]);
        As[acol4 + 0][tid >> 1] = av.x;
        As[acol4 + 1][tid >> 1] = av.y;
        As[acol4 + 2][tid >> 1] = av.z;
        As[acol4 + 3][tid >> 1] = av.w;

        float4 bv = make_float4(0.f, 0.f, 0.f, 0.f);
        if (bvalid) bv = *reinterpret_cast<const float4*>(&B[(long)(k0 + brow) * N + bcol]);
        *reinterpret_cast<float4*>(&Bs[brow][(tid & 31) * 4]) = bv;

        __syncthreads();
#pragma unroll
        for (int kk = 0; kk < 8; kk++) {
            float a[8], b[8];
            *(float4*)&a[0] = *(float4*)&As[kk][ty * 8];
            *(float4*)&a[4] = *(float4*)&As[kk][ty * 8 + 4];
            *(float4*)&b[0] = *(float4*)&Bs[kk][tx * 8];
            *(float4*)&b[4] = *(float4*)&Bs[kk][tx * 8 + 4];
#pragma unroll
            for (int i = 0; i < 8; i++)
#pragma unroll
                for (int j = 0; j < 8; j++)
                    acc[i][j] += a[i] * b[j];
        }
        __syncthreads();
    }

#pragma unroll
    for (int i = 0; i < 8; i++) {
        int m = bm + ty * 8 + i;
        if (m >= M) continue;
#pragma unroll
        for (int j = 0; j < 8; j++) {
            int n = bn + tx * 8 + j;
            if (n < N) {
                float v = acc[i][j];
                if (bias) v += bias[n];
                C[(long)m * N + n] = v;
            }
        }
    }
}

// el/er per (relation, node, head)
__global__ void k_attn_dot(const float* __restrict__ al,
                           const float* __restrict__ ar) {
    long i = (long)blockIdx.x * blockDim.x + threadIdx.x;
    if (i >= (long)R_TOTAL * N_NODES * HEADS) return;
    int h = (int)(i % HEADS);
    int n = (int)((i / HEADS) % N_NODES);
    int r = (int)(i / ((long)HEADS * N_NODES));
    const float* zp = g_z + ((long)r * N_NODES + n) * DIM_OUT + h * DHEAD;
    const float* alp = al + (r * HEADS + h) * DHEAD;
    const float* arp = ar + (r * HEADS + h) * DHEAD;
    float sl = 0.f, sr = 0.f;
#pragma unroll
    for (int d = 0; d < DHEAD; d++) {
        float zv = zp[d];
        sl += zv * alp[d];
        sr += zv * arp[d];
    }
    g_el[i] = sl;
    g_er[i] = sr;
}

__device__ __forceinline__ float edge_e(int r, int e, int h,
                                        const int* __restrict__ src,
                                        const int* __restrict__ dst,
                                        int* s_out, int* d_out_) {
    int s = src[r * N_EDGES + e];
    int d = dst[r * N_EDGES + e];
    *s_out = s; *d_out_ = d;
    float ev = g_el[((long)r * N_NODES + s) * HEADS + h] +
               g_er[((long)r * N_NODES + d) * HEADS + h];
    return (ev >= 0.f) ? ev : NEG_SLOPE * ev;
}

__global__ void k_edge_max(const int* __restrict__ src, const int* __restrict__ dst) {
    long i = (long)blockIdx.x * blockDim.x + threadIdx.x;
    if (i >= (long)R_TOTAL * N_EDGES * HEADS) return;
    int h = (int)(i % HEADS);
    int e = (int)((i / HEADS) % N_EDGES);
    int r = (int)(i / ((long)HEADS * N_EDGES));
    int s, d;
    float ev = edge_e(r, e, h, src, dst, &s, &d);
    atomicMax(&g_menc[((long)r * N_NODES + d) * HEADS + h], fenc(ev));
}

__global__ void k_edge_ex(const int* __restrict__ src, const int* __restrict__ dst) {
    long i = (long)blockIdx.x * blockDim.x + threadIdx.x;
    if (i >= (long)R_TOTAL * N_EDGES * HEADS) return;
    int h = (int)(i % HEADS);
    int e = (int)((i / HEADS) % N_EDGES);
    int r = (int)(i / ((long)HEADS * N_EDGES));
    int s, d;
    float ev = edge_e(r, e, h, src, dst, &s, &d);
    float m = fdec(g_menc[((long)r * N_NODES + d) * HEADS + h]);
    float ex = expf(ev - m);
    g_ex[i] = ex;
    atomicAdd(&g_den[((long)r * N_NODES + d) * HEADS + h], ex);
}

__global__ void k_alpha(const int* __restrict__ dst) {
    long i = (long)blockIdx.x * blockDim.x + threadIdx.x;
    if (i >= (long)R_TOTAL * N_EDGES * HEADS) return;
    int h = (int)(i % HEADS);
    int e = (int)((i / HEADS) % N_EDGES);
    int r = (int)(i / ((long)HEADS * N_EDGES));
    int d = dst[r * N_EDGES + e];
    g_ex[i] /= fmaxf(g_den[((long)r * N_NODES + d) * HEADS + h], 1e-9f);
}

__global__ void k_msg(const int* __restrict__ src, const int* __restrict__ dst) {
    long i = (long)blockIdx.x * blockDim.x + threadIdx.x;
    if (i >= (long)R_TOTAL * N_EDGES * DIM_OUT) return;
    int c = (int)(i & 127);
    int e = (int)((i >> 7) % N_EDGES);
    int r = (int)(i / ((long)N_EDGES * DIM_OUT));
    int h = c >> 5;
    int s = src[r * N_EDGES + e];
    int d = dst[r * N_EDGES + e];
    float a = g_ex[((long)r * N_EDGES + e) * HEADS + h];
    float v = a * g_z[((long)r * N_NODES + s) * DIM_OUT + c];
    atomicAdd(&g_acc[(long)d * DIM_OUT + c], v);
}

__global__ void k_finalize() {
    long i = (long)blockIdx.x * blockDim.x + threadIdx.x;
    if (i >= (long)N_NODES * DIM_OUT) return;
    int n = (int)(i / DIM_OUT);
    int c = (int)(i % DIM_OUT);
    float v = g_acc[i] * (1.0f / (float)R_TOTAL);
    g_x[(long)n * DIN + c] = (v > 0.f) ? v : 0.f;
}

__global__ void k_buildA(const int* __restrict__ root_idx,
                         const int* __restrict__ rel,
                         const float* __restrict__ sub_rel_emb,
                         const float* __restrict__ obj_rel_emb) {
    long i = (long)blockIdx.x * blockDim.x + threadIdx.x;
    if (i >= (long)2 * BATCH * KCLS) return;
    int b = (int)(i / KCLS);
    int c = (int)(i % KCLS);
    if (b < BATCH) {
        // A_sub row b: [ h[root_idx[BATCH+b]] | obj_rel_emb[rel[b]] ]
        if (c < DIM_OUT) g_A[i] = g_x[(long)root_idx[BATCH + b] * DIN + c];
        else             g_A[i] = obj_rel_emb[rel[b] * DIM_R + (c - DIM_OUT)];
    } else {
        int bb = b - BATCH;
        // A_obj row bb: [ h[root_idx[bb]] | sub_rel_emb[rel[bb]] ]
        if (c < DIM_OUT) g_A[i] = g_x[(long)root_idx[bb] * DIN + c];
        else             g_A[i] = sub_rel_emb[rel[bb] * DIM_R + (c - DIM_OUT)];
    }
}

// ---------------- launch ----------------
extern "C" void kernel_launch(void* const* d_in, const int* in_sizes, int n_in,
                              void* d_out, int out_size) {
    const int*   node_ids    = (const int*)d_in[0];
    const int*   edge_src    = (const int*)d_in[1];
    const int*   edge_dst    = (const int*)d_in[2];
    const int*   root_idx    = (const int*)d_in[3];
    const int*   rel         = (const int*)d_in[4];
    const float* entity_emb  = (const float*)d_in[5];
    const float* basis_freq  = (const float*)d_in[6];
    const float* phase       = (const float*)d_in[7];
    const float* fc_w        = (const float*)d_in[8];
    const float* attn_l      = (const float*)d_in[9];
    const float* attn_r      = (const float*)d_in[10];
    const float* sub_rel_emb = (const float*)d_in[11];
    const float* obj_rel_emb = (const float*)d_in[12];
    const float* sub_cls_w   = (const float*)d_in[13];
    const float* sub_cls_b   = (const float*)d_in[14];
    const float* obj_cls_w   = (const float*)d_in[15];
    const float* obj_cls_b   = (const float*)d_in[16];
    const int*   ts_ptr      = (n_in > 17) ? (const int*)d_in[17] : nullptr;

    float* out = (float*)d_out;

    float* px; float* pz; float* pA;
    cudaGetSymbolAddress((void**)&px, g_x);
    cudaGetSymbolAddress((void**)&pz, g_z);
    cudaGetSymbolAddress((void**)&pA, g_A);

    const int TB = 256;
    long n_init = (long)N_NODES * DIN;
    k_init<<<(unsigned)((n_init + TB - 1) / TB), TB>>>(node_ids, entity_emb, basis_freq, phase, ts_ptr);

    const long n_nodehead = (long)R_TOTAL * N_NODES * HEADS;
    const long n_edgehead = (long)R_TOTAL * N_EDGES * HEADS;
    const long n_zero     = (long)N_NODES * DIM_OUT;   // >= n_nodehead
    const long n_msg      = (long)R_TOTAL * N_EDGES * DIM_OUT;

    for (int l = 0; l < 2; l++) {
        k_zero<<<(unsigned)((n_zero + TB - 1) / TB), TB>>>();

        // z[r] = x @ fc_w[l][r]   for all 17 relations
        dim3 gz(1, (N_NODES + 127) / 128, R_TOTAL);
        sgemm128<<<gz, 256>>>(px, 0,
                              fc_w + (long)l * R_TOTAL * DIN * DIM_OUT, (long)DIN * DIM_OUT,
                              pz, (long)N_NODES * DIM_OUT,
                              nullptr, N_NODES, DIM_OUT, DIN);

        k_attn_dot<<<(unsigned)((n_nodehead + TB - 1) / TB), TB>>>(
            attn_l + (long)l * R_TOTAL * HEADS * DHEAD,
            attn_r + (long)l * R_TOTAL * HEADS * DHEAD);

        k_edge_max<<<(unsigned)((n_edgehead + TB - 1) / TB), TB>>>(edge_src, edge_dst);
        k_edge_ex<<<(unsigned)((n_edgehead + TB - 1) / TB), TB>>>(edge_src, edge_dst);
        k_alpha<<<(unsigned)((n_edgehead + TB - 1) / TB), TB>>>(edge_dst);
        k_msg<<<(unsigned)((n_msg + TB - 1) / TB), TB>>>(edge_src, edge_dst);

        k_finalize<<<(unsigned)((n_zero + TB - 1) / TB), TB>>>();
    }

    long n_bA = (long)2 * BATCH * KCLS;
    k_buildA<<<(unsigned)((n_bA + TB - 1) / TB), TB>>>(root_idx, rel, sub_rel_emb, obj_rel_emb);

    dim3 gc((NUME + 127) / 128, (BATCH + 127) / 128, 1);
    // sub_pred = A_sub @ sub_cls_w + sub_cls_b
    sgemm128<<<gc, 256>>>(pA, 0, sub_cls_w, 0, out, 0,
                          sub_cls_b, BATCH, NUME, KCLS);
    // obj_pred = A_obj @ obj_cls_w + obj_cls_b
    sgemm128<<<gc, 256>>>(pA + (long)BATCH * KCLS, 0, obj_cls_w, 0,
                          out + (long)BATCH * NUME, 0,
                          obj_cls_b, BATCH, NUME, KCLS);
    (void)in_sizes; (void)out_size;
}

// round 2
// speedup vs baseline: 1.0001x; 1.0001x over previous
#include <cuda_runtime.h>
#include <math.h>

#define NUME     30000
#define NUMR     8
#define DIM_IN   128
#define DIM_OUT  128
#define DIM_R    64
#define DIM_T    32
#define HEADS    4
#define DHEAD    32
#define R_TOTAL  17
#define N_NODES  20000
#define N_EDGES  15000
#define BATCH    1024
#define DIN      160
#define KCLS     (DIM_OUT + DIM_R)   // 192
#define NEG_SLOPE 0.2f

// ---------------- scratch (device globals; no allocation allowed) ----------------
__device__ __align__(16) float    g_x[N_NODES * DIN];                         // node features [h | phi]
__device__ __align__(16) float    g_z[(size_t)R_TOTAL * N_NODES * DIM_OUT];   // per-relation transformed feats
__device__ __align__(16) float    g_el[R_TOTAL * N_NODES * HEADS];
__device__ __align__(16) float    g_er[R_TOTAL * N_NODES * HEADS];
__device__ __align__(16) unsigned g_menc[R_TOTAL * N_NODES * HEADS];          // encoded segment max
__device__ __align__(16) float    g_den[R_TOTAL * N_NODES * HEADS];           // softmax denominator
__device__ __align__(16) float    g_ex[R_TOTAL * N_EDGES * HEADS];            // exp(e-m), then alpha in-place
__device__ __align__(16) float    g_acc[N_NODES * DIM_OUT];                   // sum over relations
__device__ __align__(16) float    g_A[2 * BATCH * KCLS];                      // classifier A matrices

// monotonic float<->uint encoding for atomicMax on signed floats
__device__ __forceinline__ unsigned fenc(float f) {
    unsigned u = __float_as_uint(f);
    return (u & 0x80000000u) ? ~u : (u | 0x80000000u);
}
__device__ __forceinline__ float fdec(unsigned u) {
    return (u & 0x80000000u) ? __uint_as_float(u & 0x7FFFFFFFu) : __uint_as_float(~u);
}

// ---------------- kernels ----------------

__global__ void k_init(const int* __restrict__ node_ids,
                       const float* __restrict__ entity_emb,
                       const float* __restrict__ basis_freq,
                       const float* __restrict__ phase,
                       const int* __restrict__ ts_ptr) {
    long i = (long)blockIdx.x * blockDim.x + threadIdx.x;
    if (i >= (long)N_NODES * DIN) return;
    int n = (int)(i / DIN);
    int c = (int)(i % DIN);
    int nid = node_ids[n];
    if (c < DIM_IN) {
        g_x[i] = entity_emb[(long)(nid % NUME) * DIM_IN + c];
    } else {
        int ts = ts_ptr ? ts_ptr[0] : 31;
        float dt = (float)(ts - 1 - nid / NUME);
        int t = c - DIM_IN;
        g_x[i] = cosf(dt * basis_freq[t] + phase[t]);
    }
}

__global__ void k_zero() {
    long i = (long)blockIdx.x * blockDim.x + threadIdx.x;
    const long NA = (long)R_TOTAL * N_NODES * HEADS;
    const long NB = (long)N_NODES * DIM_OUT;
    if (i < NA) { g_menc[i] = 0u; g_den[i] = 0.0f; }
    if (i < NB) { g_acc[i] = 0.0f; }
}

// C[z] (M x N) = A[z] (M x K, row-major, lda=K) @ B[z] (K x N, row-major, ldb=N) (+ bias)
__global__ __launch_bounds__(256) void sgemm128(
    const float* __restrict__ Aall, long sA,
    const float* __restrict__ Ball, long sB,
    float* __restrict__ Call, long sC,
    const float* __restrict__ bias,
    int M, int N, int K) {
    const float* A = Aall + sA * blockIdx.z;
    const float* B = Ball + sB * blockIdx.z;
    float* C = Call + sC * blockIdx.z;
    int bm = blockIdx.y * 128;
    int bn = blockIdx.x * 128;
    int tid = threadIdx.x;
    int tx = tid & 15, ty = tid >> 4;

    __shared__ float As[8][128];
    __shared__ float Bs[8][128];

    float acc[8][8];
#pragma unroll
    for (int i = 0; i < 8; i++)
#pragma unroll
        for (int j = 0; j < 8; j++) acc[i][j] = 0.0f;

    int arow = bm + (tid >> 1);
    int acol4 = (tid & 1) * 4;
    int brow = tid >> 5;
    int bcol = bn + (tid & 31) * 4;
    bool avalid = (arow < M);
    bool bvalid = (bcol + 3) < N;   // N is a multiple of 4 in all uses

    for (int k0 = 0; k0 < K; k0 += 8) {
        float4 av = make_float4(0.f, 0.f, 0.f, 0.f);
        if (avalid) av = *reinterpret_cast<const float4*>(&A[(long)arow * K + k0 + acol4]);
        As[acol4 + 0][tid >> 1] = av.x;
        As[acol4 + 1][tid >> 1] = av.y;
        As[acol4 + 2][tid >> 1] = av.z;
        As[acol4 + 3][tid >> 1] = av.w;

        float4 bv = make_float4(0.f, 0.f, 0.f, 0.f);
        if (bvalid) bv = *reinterpret_cast<const float4*>(&B[(long)(k0 + brow) * N + bcol]);
        *reinterpret_cast<float4*>(&Bs[brow][(tid & 31) * 4]) = bv;

        __syncthreads();
#pragma unroll
        for (int kk = 0; kk < 8; kk++) {
            float a[8], b[8];
            *(float4*)&a[0] = *(float4*)&As[kk][ty * 8];
            *(float4*)&a[4] = *(float4*)&As[kk][ty * 8 + 4];
            *(float4*)&b[0] = *(float4*)&Bs[kk][tx * 8];
            *(float4*)&b[4] = *(float4*)&Bs[kk][tx * 8 + 4];
#pragma unroll
            for (int i = 0; i < 8; i++)
#pragma unroll
                for (int j = 0; j < 8; j++)
                    acc[i][j] += a[i] * b[j];
        }
        __syncthreads();
    }

#pragma unroll
    for (int i = 0; i < 8; i++) {
        int m = bm + ty * 8 + i;
        if (m >= M) continue;
#pragma unroll
        for (int j = 0; j < 8; j++) {
            int n = bn + tx * 8 + j;
            if (n < N) {
                float v = acc[i][j];
                if (bias) v += bias[n];
                C[(long)m * N + n] = v;
            }
        }
    }
}

// el/er per (relation, node, head)
__global__ void k_attn_dot(const float* __restrict__ al,
                           const float* __restrict__ ar) {
    long i = (long)blockIdx.x * blockDim.x + threadIdx.x;
    if (i >= (long)R_TOTAL * N_NODES * HEADS) return;
    int h = (int)(i % HEADS);
    int n = (int)((i / HEADS) % N_NODES);
    int r = (int)(i / ((long)HEADS * N_NODES));
    const float* zp = g_z + ((long)r * N_NODES + n) * DIM_OUT + h * DHEAD;
    const float* alp = al + (r * HEADS + h) * DHEAD;
    const float* arp = ar + (r * HEADS + h) * DHEAD;
    float sl = 0.f, sr = 0.f;
#pragma unroll
    for (int d = 0; d < DHEAD; d++) {
        float zv = zp[d];
        sl += zv * alp[d];
        sr += zv * arp[d];
    }
    g_el[i] = sl;
    g_er[i] = sr;
}

__device__ __forceinline__ float edge_e(int r, int e, int h,
                                        const int* __restrict__ src,
                                        const int* __restrict__ dst,
                                        int* s_out, int* d_out_) {
    int s = src[r * N_EDGES + e];
    int d = dst[r * N_EDGES + e];
    *s_out = s; *d_out_ = d;
    float ev = g_el[((long)r * N_NODES + s) * HEADS + h] +
               g_er[((long)r * N_NODES + d) * HEADS + h];
    return (ev >= 0.f) ? ev : NEG_SLOPE * ev;
}

__global__ void k_edge_max(const int* __restrict__ src, const int* __restrict__ dst) {
    long i = (long)blockIdx.x * blockDim.x + threadIdx.x;
    if (i >= (long)R_TOTAL * N_EDGES * HEADS) return;
    int h = (int)(i % HEADS);
    int e = (int)((i / HEADS) % N_EDGES);
    int r = (int)(i / ((long)HEADS * N_EDGES));
    int s, d;
    float ev = edge_e(r, e, h, src, dst, &s, &d);
    atomicMax(&g_menc[((long)r * N_NODES + d) * HEADS + h], fenc(ev));
}

__global__ void k_edge_ex(const int* __restrict__ src, const int* __restrict__ dst) {
    long i = (long)blockIdx.x * blockDim.x + threadIdx.x;
    if (i >= (long)R_TOTAL * N_EDGES * HEADS) return;
    int h = (int)(i % HEADS);
    int e = (int)((i / HEADS) % N_EDGES);
    int r = (int)(i / ((long)HEADS * N_EDGES));
    int s, d;
    float ev = edge_e(r, e, h, src, dst, &s, &d);
    float m = fdec(g_menc[((long)r * N_NODES + d) * HEADS + h]);
    float ex = expf(ev - m);
    g_ex[i] = ex;
    atomicAdd(&g_den[((long)r * N_NODES + d) * HEADS + h], ex);
}

__global__ void k_alpha(const int* __restrict__ dst) {
    long i = (long)blockIdx.x * blockDim.x + threadIdx.x;
    if (i >= (long)R_TOTAL * N_EDGES * HEADS) return;
    int h = (int)(i % HEADS);
    int e = (int)((i / HEADS) % N_EDGES);
    int r = (int)(i / ((long)HEADS * N_EDGES));
    int d = dst[r * N_EDGES + e];
    g_ex[i] /= fmaxf(g_den[((long)r * N_NODES + d) * HEADS + h], 1e-9f);
}

__global__ void k_msg(const int* __restrict__ src, const int* __restrict__ dst) {
    long i = (long)blockIdx.x * blockDim.x + threadIdx.x;
    if (i >= (long)R_TOTAL * N_EDGES * DIM_OUT) return;
    int c = (int)(i & 127);
    int e = (int)((i >> 7) % N_EDGES);
    int r = (int)(i / ((long)N_EDGES * DIM_OUT));
    int h = c >> 5;
    int s = src[r * N_EDGES + e];
    int d = dst[r * N_EDGES + e];
    float a = g_ex[((long)r * N_EDGES + e) * HEADS + h];
    float v = a * g_z[((long)r * N_NODES + s) * DIM_OUT + c];
    atomicAdd(&g_acc[(long)d * DIM_OUT + c], v);
}

__global__ void k_finalize() {
    long i = (long)blockIdx.x * blockDim.x + threadIdx.x;
    if (i >= (long)N_NODES * DIM_OUT) return;
    int n = (int)(i / DIM_OUT);
    int c = (int)(i % DIM_OUT);
    float v = g_acc[i] * (1.0f / (float)R_TOTAL);
    g_x[(long)n * DIN + c] = (v > 0.f) ? v : 0.f;
}

__global__ void k_buildA(const int* __restrict__ root_idx,
                         const int* __restrict__ rel,
                         const float* __restrict__ sub_rel_emb,
                         const float* __restrict__ obj_rel_emb) {
    long i = (long)blockIdx.x * blockDim.x + threadIdx.x;
    if (i >= (long)2 * BATCH * KCLS) return;
    int b = (int)(i / KCLS);
    int c = (int)(i % KCLS);
    if (b < BATCH) {
        // A_sub row b: [ h[root_idx[BATCH+b]] | obj_rel_emb[rel[b]] ]
        if (c < DIM_OUT) g_A[i] = g_x[(long)root_idx[BATCH + b] * DIN + c];
        else             g_A[i] = obj_rel_emb[rel[b] * DIM_R + (c - DIM_OUT)];
    } else {
        int bb = b - BATCH;
        // A_obj row bb: [ h[root_idx[bb]] | sub_rel_emb[rel[bb]] ]
        if (c < DIM_OUT) g_A[i] = g_x[(long)root_idx[bb] * DIN + c];
        else             g_A[i] = sub_rel_emb[rel[bb] * DIM_R + (c - DIM_OUT)];
    }
}

// ---------------- launch ----------------
extern "C" void kernel_launch(void* const* d_in, const int* in_sizes, int n_in,
                              void* d_out, int out_size) {
    const int*   node_ids    = (const int*)d_in[0];
    const int*   edge_src    = (const int*)d_in[1];
    const int*   edge_dst    = (const int*)d_in[2];
    const int*   root_idx    = (const int*)d_in[3];
    const int*   rel         = (const int*)d_in[4];
    const float* entity_emb  = (const float*)d_in[5];
    const float* basis_freq  = (const float*)d_in[6];
    const float* phase       = (const float*)d_in[7];
    const float* fc_w        = (const float*)d_in[8];
    const float* attn_l      = (const float*)d_in[9];
    const float* attn_r      = (const float*)d_in[10];
    const float* sub_rel_emb = (const float*)d_in[11];
    const float* obj_rel_emb = (const float*)d_in[12];
    const float* sub_cls_w   = (const float*)d_in[13];
    const float* sub_cls_b   = (const float*)d_in[14];
    const float* obj_cls_w   = (const float*)d_in[15];
    const float* obj_cls_b   = (const float*)d_in[16];
    const int*   ts_ptr      = (n_in > 17) ? (const int*)d_in[17] : nullptr;

    float* out = (float*)d_out;

    float* px; float* pz; float* pA;
    cudaGetSymbolAddress((void**)&px, g_x);
    cudaGetSymbolAddress((void**)&pz, g_z);
    cudaGetSymbolAddress((void**)&pA, g_A);

    const int TB = 256;
    long n_init = (long)N_NODES * DIN;
    k_init<<<(unsigned)((n_init + TB - 1) / TB), TB>>>(node_ids, entity_emb, basis_freq, phase, ts_ptr);

    const long n_nodehead = (long)R_TOTAL * N_NODES * HEADS;
    const long n_edgehead = (long)R_TOTAL * N_EDGES * HEADS;
    const long n_zero     = (long)N_NODES * DIM_OUT;   // >= n_nodehead
    const long n_msg      = (long)R_TOTAL * N_EDGES * DIM_OUT;

    for (int l = 0; l < 2; l++) {
        k_zero<<<(unsigned)((n_zero + TB - 1) / TB), TB>>>();

        // z[r] = x @ fc_w[l][r]   for all 17 relations
        dim3 gz(1, (N_NODES + 127) / 128, R_TOTAL);
        sgemm128<<<gz, 256>>>(px, 0,
                              fc_w + (long)l * R_TOTAL * DIN * DIM_OUT, (long)DIN * DIM_OUT,
                              pz, (long)N_NODES * DIM_OUT,
                              nullptr, N_NODES, DIM_OUT, DIN);

        k_attn_dot<<<(unsigned)((n_nodehead + TB - 1) / TB), TB>>>(
            attn_l + (long)l * R_TOTAL * HEADS * DHEAD,
            attn_r + (long)l * R_TOTAL * HEADS * DHEAD);

        k_edge_max<<<(unsigned)((n_edgehead + TB - 1) / TB), TB>>>(edge_src, edge_dst);
        k_edge_ex<<<(unsigned)((n_edgehead + TB - 1) / TB), TB>>>(edge_src, edge_dst);
        k_alpha<<<(unsigned)((n_edgehead + TB - 1) / TB), TB>>>(edge_dst);
        k_msg<<<(unsigned)((n_msg + TB - 1) / TB), TB>>>(edge_src, edge_dst);

        k_finalize<<<(unsigned)((n_zero + TB - 1) / TB), TB>>>();
    }

    long n_bA = (long)2 * BATCH * KCLS;
    k_buildA<<<(unsigned)((n_bA + TB - 1) / TB), TB>>>(root_idx, rel, sub_rel_emb, obj_rel_emb);

    dim3 gc((NUME + 127) / 128, (BATCH + 127) / 128, 1);
    // sub_pred = A_sub @ sub_cls_w + sub_cls_b
    sgemm128<<<gc, 256>>>(pA, 0, sub_cls_w, 0, out, 0,
                          sub_cls_b, BATCH, NUME, KCLS);
    // obj_pred = A_obj @ obj_cls_w + obj_cls_b
    sgemm128<<<gc, 256>>>(pA + (long)BATCH * KCLS, 0, obj_cls_w, 0,
                          out + (long)BATCH * NUME, 0,
                          obj_cls_b, BATCH, NUME, KCLS);
    (void)in_sizes; (void)out_size;
}

// round 3
// speedup vs baseline: 1.6027x; 1.6026x over previous
#include <cuda_runtime.h>
#include <math.h>

#define NUME     30000
#define NUMR     8
#define DIM_IN   128
#define DIM_OUT  128
#define DIM_R    64
#define DIM_T    32
#define HEADS    4
#define DHEAD    32
#define R_TOTAL  17
#define N_NODES  20000
#define N_EDGES  15000
#define BATCH    1024
#define DIN      160
#define KCLS     (DIM_OUT + DIM_R)   // 192
#define NEG_SLOPE 0.2f

// ---------------- scratch (device globals; no allocation allowed) ----------------
__device__ __align__(16) float    g_x[N_NODES * DIN];                         // node features [h | phi]
__device__ __align__(16) float    g_z[(size_t)R_TOTAL * N_NODES * DIM_OUT];   // per-relation transformed feats
__device__ __align__(16) float    g_el[R_TOTAL * N_NODES * HEADS];
__device__ __align__(16) float    g_er[R_TOTAL * N_NODES * HEADS];
__device__ __align__(16) unsigned g_menc[R_TOTAL * N_NODES * HEADS];          // encoded segment max
__device__ __align__(16) float    g_den[R_TOTAL * N_NODES * HEADS];           // softmax denominator
__device__ __align__(16) float    g_ex[R_TOTAL * N_EDGES * HEADS];            // exp(e-m) (unnormalized)
__device__ __align__(16) float    g_acc[N_NODES * DIM_OUT];                   // sum over relations
__device__ __align__(16) float    g_A[2 * BATCH * KCLS];                      // classifier A matrices

// monotonic float<->uint encoding for atomicMax on signed floats
__device__ __forceinline__ unsigned fenc(float f) {
    unsigned u = __float_as_uint(f);
    return (u & 0x80000000u) ? ~u : (u | 0x80000000u);
}
__device__ __forceinline__ float fdec(unsigned u) {
    return (u & 0x80000000u) ? __uint_as_float(u & 0x7FFFFFFFu) : __uint_as_float(~u);
}

__device__ __forceinline__ unsigned f2tf32(float f) {
    unsigned r;
    asm("cvt.rna.tf32.f32 %0, %1;" : "=r"(r) : "f"(f));
    return r;
}

// ---------------- kernels ----------------

__global__ void k_init(const int* __restrict__ node_ids,
                       const float* __restrict__ entity_emb,
                       const float* __restrict__ basis_freq,
                       const float* __restrict__ phase,
                       const int* __restrict__ ts_ptr) {
    long i = (long)blockIdx.x * blockDim.x + threadIdx.x;
    if (i >= (long)N_NODES * DIN) return;
    int n = (int)(i / DIN);
    int c = (int)(i % DIN);
    int nid = node_ids[n];
    if (c < DIM_IN) {
        g_x[i] = entity_emb[(long)(nid % NUME) * DIM_IN + c];
    } else {
        int ts = ts_ptr ? ts_ptr[0] : 31;
        float dt = (float)(ts - 1 - nid / NUME);
        int t = c - DIM_IN;
        g_x[i] = cosf(dt * basis_freq[t] + phase[t]);
    }
}

__global__ void k_zero() {
    long i = (long)blockIdx.x * blockDim.x + threadIdx.x;
    const long NA = (long)R_TOTAL * N_NODES * HEADS;
    const long NB = (long)N_NODES * DIM_OUT;
    if (i < NA) { g_menc[i] = 0u; g_den[i] = 0.0f; }
    if (i < NB) { g_acc[i] = 0.0f; }
}

// ---------------- tf32 tensor-core GEMM ----------------
// C[z] (M x N) = A[z] (M x K, row-major) @ B[z] (K x N, row-major) (+ bias)
// 128x128 block tile, BK=16, 8 warps (each 64x32), mma.m16n8k8.tf32.
// Requires K % 16 == 0, N % 4 == 0.
__global__ __launch_bounds__(256) void tfgemm(
    const float* __restrict__ Aall, long sA,
    const float* __restrict__ Ball, long sB,
    float* __restrict__ Call, long sC,
    const float* __restrict__ bias,
    int M, int N, int K) {
    const float* A = Aall + sA * blockIdx.z;
    const float* B = Ball + sB * blockIdx.z;
    float* C = Call + sC * blockIdx.z;
    const int bm = blockIdx.y * 128;
    const int bn = blockIdx.x * 128;
    const int tid  = threadIdx.x;
    const int warp = tid >> 5;
    const int lane = tid & 31;
    const int wm = warp & 1;       // 2 warps along M (64 each)
    const int wn = warp >> 1;      // 4 warps along N (32 each)
    const int gid = lane >> 2;     // 0..7
    const int tig = lane & 3;      // 0..3

    __shared__ unsigned As[16][136];   // [k][m], pad 8 -> conflict-free frag loads
    __shared__ unsigned Bs[16][136];   // [k][n]

    float acc[4][4][4];
#pragma unroll
    for (int i = 0; i < 4; i++)
#pragma unroll
        for (int j = 0; j < 4; j++)
#pragma unroll
            for (int q = 0; q < 4; q++) acc[i][j][q] = 0.0f;

    // A tile load mapping: row = tid>>1 (0..127), 8 cols starting at (tid&1)*8
    const int arow  = tid >> 1;
    const int acolg = (tid & 1) * 8;
    const bool avalid = (bm + arow) < M;

    for (int k0 = 0; k0 < K; k0 += 16) {
        // ---- load A tile (128 x 16) ----
        float4 av0 = make_float4(0.f, 0.f, 0.f, 0.f);
        float4 av1 = make_float4(0.f, 0.f, 0.f, 0.f);
        if (avalid) {
            const float* ap = &A[(long)(bm + arow) * K + k0 + acolg];
            av0 = *reinterpret_cast<const float4*>(ap);
            av1 = *reinterpret_cast<const float4*>(ap + 4);
        }
        As[acolg + 0][arow] = f2tf32(av0.x);
        As[acolg + 1][arow] = f2tf32(av0.y);
        As[acolg + 2][arow] = f2tf32(av0.z);
        As[acolg + 3][arow] = f2tf32(av0.w);
        As[acolg + 4][arow] = f2tf32(av1.x);
        As[acolg + 5][arow] = f2tf32(av1.y);
        As[acolg + 6][arow] = f2tf32(av1.z);
        As[acolg + 7][arow] = f2tf32(av1.w);

        // ---- load B tile (16 x 128) ----
#pragma unroll
        for (int t = tid; t < 512; t += 256) {
            int r  = t >> 5;            // k row 0..15
            int c4 = (t & 31) * 4;      // col group
            float4 bv = make_float4(0.f, 0.f, 0.f, 0.f);
            if (bn + c4 + 3 < N)
                bv = *reinterpret_cast<const float4*>(&B[(long)(k0 + r) * N + bn + c4]);
            Bs[r][c4 + 0] = f2tf32(bv.x);
            Bs[r][c4 + 1] = f2tf32(bv.y);
            Bs[r][c4 + 2] = f2tf32(bv.z);
            Bs[r][c4 + 3] = f2tf32(bv.w);
        }
        __syncthreads();

#pragma unroll
        for (int ks = 0; ks < 16; ks += 8) {
            unsigned af[4][4], bf[4][2];
#pragma unroll
            for (int mi = 0; mi < 4; mi++) {
                int mrow = wm * 64 + mi * 16 + gid;
                af[mi][0] = As[ks + tig][mrow];
                af[mi][1] = As[ks + tig][mrow + 8];
                af[mi][2] = As[ks + tig + 4][mrow];
                af[mi][3] = As[ks + tig + 4][mrow + 8];
            }
#pragma unroll
            for (int nj = 0; nj < 4; nj++) {
                int ncol = wn * 32 + nj * 8 + gid;
                bf[nj][0] = Bs[ks + tig][ncol];
                bf[nj][1] = Bs[ks + tig + 4][ncol];
            }
#pragma unroll
            for (int mi = 0; mi < 4; mi++)
#pragma unroll
                for (int nj = 0; nj < 4; nj++) {
                    asm volatile(
                        "mma.sync.aligned.m16n8k8.row.col.f32.tf32.tf32.f32 "
                        "{%0,%1,%2,%3}, {%4,%5,%6,%7}, {%8,%9}, {%0,%1,%2,%3};"
                        : "+f"(acc[mi][nj][0]), "+f"(acc[mi][nj][1]),
                          "+f"(acc[mi][nj][2]), "+f"(acc[mi][nj][3])
                        : "r"(af[mi][0]), "r"(af[mi][1]), "r"(af[mi][2]), "r"(af[mi][3]),
                          "r"(bf[nj][0]), "r"(bf[nj][1]));
                }
        }
        __syncthreads();
    }

    // ---- epilogue ----
#pragma unroll
    for (int mi = 0; mi < 4; mi++) {
        int m0 = bm + wm * 64 + mi * 16 + gid;
#pragma unroll
        for (int nj = 0; nj < 4; nj++) {
            int n0 = bn + wn * 32 + nj * 8 + tig * 2;
            if (n0 < N) {
                float b0 = bias ? bias[n0]     : 0.f;
                float b1 = bias ? bias[n0 + 1] : 0.f;
                if (m0 < M) {
                    C[(long)m0 * N + n0]     = acc[mi][nj][0] + b0;
                    C[(long)m0 * N + n0 + 1] = acc[mi][nj][1] + b1;
                }
                if (m0 + 8 < M) {
                    C[(long)(m0 + 8) * N + n0]     = acc[mi][nj][2] + b0;
                    C[(long)(m0 + 8) * N + n0 + 1] = acc[mi][nj][3] + b1;
                }
            }
        }
    }
}

// el/er per (relation, node): one warp per (r,n), coalesced z reads + shfl reduce
__global__ void k_attn_dot(const float* __restrict__ al,
                           const float* __restrict__ ar) {
    long gw = ((long)blockIdx.x * blockDim.x + threadIdx.x) >> 5;
    int lane = threadIdx.x & 31;
    if (gw >= (long)R_TOTAL * N_NODES) return;
    int r = (int)(gw / N_NODES);
    const float* zp = g_z + gw * DIM_OUT;
#pragma unroll
    for (int h = 0; h < HEADS; h++) {
        float zv = zp[h * 32 + lane];
        float sl = zv * al[(r * HEADS + h) * DHEAD + lane];
        float sr = zv * ar[(r * HEADS + h) * DHEAD + lane];
#pragma unroll
        for (int o = 16; o; o >>= 1) {
            sl += __shfl_xor_sync(0xFFFFFFFFu, sl, o);
            sr += __shfl_xor_sync(0xFFFFFFFFu, sr, o);
        }
        if (lane == 0) {
            g_el[gw * HEADS + h] = sl;
            g_er[gw * HEADS + h] = sr;
        }
    }
}

__device__ __forceinline__ float edge_e(int r, int e, int h,
                                        const int* __restrict__ src,
                                        const int* __restrict__ dst,
                                        int* s_out, int* d_out_) {
    int s = src[r * N_EDGES + e];
    int d = dst[r * N_EDGES + e];
    *s_out = s; *d_out_ = d;
    float ev = g_el[((long)r * N_NODES + s) * HEADS + h] +
               g_er[((long)r * N_NODES + d) * HEADS + h];
    return (ev >= 0.f) ? ev : NEG_SLOPE * ev;
}

__global__ void k_edge_max(const int* __restrict__ src, const int* __restrict__ dst) {
    long i = (long)blockIdx.x * blockDim.x + threadIdx.x;
    if (i >= (long)R_TOTAL * N_EDGES * HEADS) return;
    int h = (int)(i % HEADS);
    int e = (int)((i / HEADS) % N_EDGES);
    int r = (int)(i / ((long)HEADS * N_EDGES));
    int s, d;
    float ev = edge_e(r, e, h, src, dst, &s, &d);
    atomicMax(&g_menc[((long)r * N_NODES + d) * HEADS + h], fenc(ev));
}

__global__ void k_edge_ex(const int* __restrict__ src, const int* __restrict__ dst) {
    long i = (long)blockIdx.x * blockDim.x + threadIdx.x;
    if (i >= (long)R_TOTAL * N_EDGES * HEADS) return;
    int h = (int)(i % HEADS);
    int e = (int)((i / HEADS) % N_EDGES);
    int r = (int)(i / ((long)HEADS * N_EDGES));
    int s, d;
    float ev = edge_e(r, e, h, src, dst, &s, &d);
    float m = fdec(g_menc[((long)r * N_NODES + d) * HEADS + h]);
    float ex = expf(ev - m);
    g_ex[i] = ex;
    atomicAdd(&g_den[((long)r * N_NODES + d) * HEADS + h], ex);
}

// message + scatter, alpha normalization fused (reads den directly)
__global__ void k_msg(const int* __restrict__ src, const int* __restrict__ dst) {
    long i = (long)blockIdx.x * blockDim.x + threadIdx.x;
    if (i >= (long)R_TOTAL * N_EDGES * DIM_OUT) return;
    int c = (int)(i & 127);
    int e = (int)((i >> 7) % N_EDGES);
    int r = (int)(i / ((long)N_EDGES * DIM_OUT));
    int h = c >> 5;
    int s = src[r * N_EDGES + e];
    int d = dst[r * N_EDGES + e];
    float ex = g_ex[((long)r * N_EDGES + e) * HEADS + h];
    float den = fmaxf(g_den[((long)r * N_NODES + d) * HEADS + h], 1e-9f);
    float v = (ex / den) * g_z[((long)r * N_NODES + s) * DIM_OUT + c];
    atomicAdd(&g_acc[(long)d * DIM_OUT + c], v);
}

__global__ void k_finalize() {
    long i = (long)blockIdx.x * blockDim.x + threadIdx.x;
    if (i >= (long)N_NODES * DIM_OUT) return;
    int n = (int)(i / DIM_OUT);
    int c = (int)(i % DIM_OUT);
    float v = g_acc[i] * (1.0f / (float)R_TOTAL);
    g_x[(long)n * DIN + c] = (v > 0.f) ? v : 0.f;
}

__global__ void k_buildA(const int* __restrict__ root_idx,
                         const int* __restrict__ rel,
                         const float* __restrict__ sub_rel_emb,
                         const float* __restrict__ obj_rel_emb) {
    long i = (long)blockIdx.x * blockDim.x + threadIdx.x;
    if (i >= (long)2 * BATCH * KCLS) return;
    int b = (int)(i / KCLS);
    int c = (int)(i % KCLS);
    if (b < BATCH) {
        if (c < DIM_OUT) g_A[i] = g_x[(long)root_idx[BATCH + b] * DIN + c];
        else             g_A[i] = obj_rel_emb[rel[b] * DIM_R + (c - DIM_OUT)];
    } else {
        int bb = b - BATCH;
        if (c < DIM_OUT) g_A[i] = g_x[(long)root_idx[bb] * DIN + c];
        else             g_A[i] = sub_rel_emb[rel[bb] * DIM_R + (c - DIM_OUT)];
    }
}

// ---------------- launch ----------------
extern "C" void kernel_launch(void* const* d_in, const int* in_sizes, int n_in,
                              void* d_out, int out_size) {
    const int*   node_ids    = (const int*)d_in[0];
    const int*   edge_src    = (const int*)d_in[1];
    const int*   edge_dst    = (const int*)d_in[2];
    const int*   root_idx    = (const int*)d_in[3];
    const int*   rel         = (const int*)d_in[4];
    const float* entity_emb  = (const float*)d_in[5];
    const float* basis_freq  = (const float*)d_in[6];
    const float* phase       = (const float*)d_in[7];
    const float* fc_w        = (const float*)d_in[8];
    const float* attn_l      = (const float*)d_in[9];
    const float* attn_r      = (const float*)d_in[10];
    const float* sub_rel_emb = (const float*)d_in[11];
    const float* obj_rel_emb = (const float*)d_in[12];
    const float* sub_cls_w   = (const float*)d_in[13];
    const float* sub_cls_b   = (const float*)d_in[14];
    const float* obj_cls_w   = (const float*)d_in[15];
    const float* obj_cls_b   = (const float*)d_in[16];
    const int*   ts_ptr      = (n_in > 17) ? (const int*)d_in[17] : nullptr;

    float* out = (float*)d_out;

    float* px; float* pz; float* pA;
    cudaGetSymbolAddress((void**)&px, g_x);
    cudaGetSymbolAddress((void**)&pz, g_z);
    cudaGetSymbolAddress((void**)&pA, g_A);

    const int TB = 256;
    long n_init = (long)N_NODES * DIN;
    k_init<<<(unsigned)((n_init + TB - 1) / TB), TB>>>(node_ids, entity_emb, basis_freq, phase, ts_ptr);

    const long n_warps    = (long)R_TOTAL * N_NODES;           // attn_dot: 1 warp each
    const long n_edgehead = (long)R_TOTAL * N_EDGES * HEADS;
    const long n_zero     = (long)N_NODES * DIM_OUT;
    const long n_msg      = (long)R_TOTAL * N_EDGES * DIM_OUT;

    for (int l = 0; l < 2; l++) {
        k_zero<<<(unsigned)((n_zero + TB - 1) / TB), TB>>>();

        // z[r] = x @ fc_w[l][r]   for all 17 relations (tensor cores, tf32)
        dim3 gz(1, (N_NODES + 127) / 128, R_TOTAL);
        tfgemm<<<gz, 256>>>(px, 0,
                            fc_w + (long)l * R_TOTAL * DIN * DIM_OUT, (long)DIN * DIM_OUT,
                            pz, (long)N_NODES * DIM_OUT,
                            nullptr, N_NODES, DIM_OUT, DIN);

        k_attn_dot<<<(unsigned)((n_warps * 32 + TB - 1) / TB), TB>>>(
            attn_l + (long)l * R_TOTAL * HEADS * DHEAD,
            attn_r + (long)l * R_TOTAL * HEADS * DHEAD);

        k_edge_max<<<(unsigned)((n_edgehead + TB - 1) / TB), TB>>>(edge_src, edge_dst);
        k_edge_ex<<<(unsigned)((n_edgehead + TB - 1) / TB), TB>>>(edge_src, edge_dst);
        k_msg<<<(unsigned)((n_msg + TB - 1) / TB), TB>>>(edge_src, edge_dst);

        k_finalize<<<(unsigned)((n_zero + TB - 1) / TB), TB>>>();
    }

    long n_bA = (long)2 * BATCH * KCLS;
    k_buildA<<<(unsigned)((n_bA + TB - 1) / TB), TB>>>(root_idx, rel, sub_rel_emb, obj_rel_emb);

    dim3 gc((NUME + 127) / 128, (BATCH + 127) / 128, 1);
    // sub_pred = A_sub @ sub_cls_w + sub_cls_b   (tensor cores, tf32)
    tfgemm<<<gc, 256>>>(pA, 0, sub_cls_w, 0, out, 0,
                        sub_cls_b, BATCH, NUME, KCLS);
    // obj_pred = A_obj @ obj_cls_w + obj_cls_b
    tfgemm<<<gc, 256>>>(pA + (long)BATCH * KCLS, 0, obj_cls_w, 0,
                        out + (long)BATCH * NUME, 0,
                        obj_cls_b, BATCH, NUME, KCLS);
    (void)in_sizes; (void)out_size;
}

// round 4
// speedup vs baseline: 1.6217x; 1.0119x over previous
#include <cuda_runtime.h>
#include <math.h>

#define NUME     30000
#define NUMR     8
#define DIM_IN   128
#define DIM_OUT  128
#define DIM_R    64
#define DIM_T    32
#define HEADS    4
#define DHEAD    32
#define R_TOTAL  17
#define N_NODES  20000
#define N_EDGES  15000
#define BATCH    1024
#define DIN      160
#define KCLS     (DIM_OUT + DIM_R)   // 192
#define NEG_SLOPE 0.2f

// ---------------- scratch (device globals; no allocation allowed) ----------------
__device__ __align__(16) float    g_x[N_NODES * DIN];                         // node features [h | phi]
__device__ __align__(16) float    g_z[(size_t)R_TOTAL * N_NODES * DIM_OUT];   // per-relation transformed feats
__device__ __align__(16) float    g_el[R_TOTAL * N_NODES * HEADS];
__device__ __align__(16) float    g_er[R_TOTAL * N_NODES * HEADS];
__device__ __align__(16) unsigned g_menc[R_TOTAL * N_NODES * HEADS];          // encoded segment max
__device__ __align__(16) float    g_den[R_TOTAL * N_NODES * HEADS];           // softmax denominator
__device__ __align__(16) float    g_ex[R_TOTAL * N_EDGES * HEADS];            // exp(e-m) (unnormalized)
__device__ __align__(16) float    g_acc[N_NODES * DIM_OUT];                   // sum over relations
__device__ __align__(16) float    g_A[2 * BATCH * KCLS];                      // classifier A matrices

// monotonic float<->uint encoding for atomicMax on signed floats
__device__ __forceinline__ unsigned fenc(float f) {
    unsigned u = __float_as_uint(f);
    return (u & 0x80000000u) ? ~u : (u | 0x80000000u);
}
__device__ __forceinline__ float fdec(unsigned u) {
    return (u & 0x80000000u) ? __uint_as_float(u & 0x7FFFFFFFu) : __uint_as_float(~u);
}

__device__ __forceinline__ unsigned f2tf32(float f) {
    unsigned r;
    asm("cvt.rna.tf32.f32 %0, %1;" : "=r"(r) : "f"(f));
    return r;
}

// ---------------- kernels ----------------

__global__ void k_init(const int* __restrict__ node_ids,
                       const float* __restrict__ entity_emb,
                       const float* __restrict__ basis_freq,
                       const float* __restrict__ phase,
                       const int* __restrict__ ts_ptr) {
    long i = (long)blockIdx.x * blockDim.x + threadIdx.x;
    if (i >= (long)N_NODES * DIN) return;
    int n = (int)(i / DIN);
    int c = (int)(i % DIN);
    int nid = node_ids[n];
    if (c < DIM_IN) {
        g_x[i] = entity_emb[(long)(nid % NUME) * DIM_IN + c];
    } else {
        int ts = ts_ptr ? ts_ptr[0] : 31;
        float dt = (float)(ts - 1 - nid / NUME);
        int t = c - DIM_IN;
        g_x[i] = cosf(dt * basis_freq[t] + phase[t]);
    }
}

__global__ void k_zero() {
    long i = (long)blockIdx.x * blockDim.x + threadIdx.x;
    const long NA = (long)R_TOTAL * N_NODES * HEADS;
    const long NB = (long)N_NODES * DIM_OUT;
    if (i < NA) { g_menc[i] = 0u; g_den[i] = 0.0f; }
    if (i < NB) { g_acc[i] = 0.0f; }
}

// ---------------- tf32 tensor-core GEMM ----------------
// C[z] (M x N) = A[z] (M x K, row-major) @ B[z] (K x N, row-major) (+ bias)
// 128x128 block tile, BK=16, 8 warps (each 64x32), mma.m16n8k8.tf32.
// Requires K % 16 == 0, N % 4 == 0.
__global__ __launch_bounds__(256) void tfgemm(
    const float* __restrict__ Aall, long sA,
    const float* __restrict__ Ball, long sB,
    float* __restrict__ Call, long sC,
    const float* __restrict__ bias,
    int M, int N, int K) {
    const float* A = Aall + sA * blockIdx.z;
    const float* B = Ball + sB * blockIdx.z;
    float* C = Call + sC * blockIdx.z;
    const int bm = blockIdx.y * 128;
    const int bn = blockIdx.x * 128;
    const int tid  = threadIdx.x;
    const int warp = tid >> 5;
    const int lane = tid & 31;
    const int wm = warp & 1;       // 2 warps along M (64 each)
    const int wn = warp >> 1;      // 4 warps along N (32 each)
    const int gid = lane >> 2;     // 0..7
    const int tig = lane & 3;      // 0..3

    __shared__ unsigned As[16][136];   // [k][m], pad 8 -> conflict-free frag loads
    __shared__ unsigned Bs[16][136];   // [k][n]

    float acc[4][4][4];
#pragma unroll
    for (int i = 0; i < 4; i++)
#pragma unroll
        for (int j = 0; j < 4; j++)
#pragma unroll
            for (int q = 0; q < 4; q++) acc[i][j][q] = 0.0f;

    // A tile load mapping: row = tid>>1 (0..127), 8 cols starting at (tid&1)*8
    const int arow  = tid >> 1;
    const int acolg = (tid & 1) * 8;
    const bool avalid = (bm + arow) < M;

    for (int k0 = 0; k0 < K; k0 += 16) {
        // ---- load A tile (128 x 16) ----
        float4 av0 = make_float4(0.f, 0.f, 0.f, 0.f);
        float4 av1 = make_float4(0.f, 0.f, 0.f, 0.f);
        if (avalid) {
            const float* ap = &A[(long)(bm + arow) * K + k0 + acolg];
            av0 = *reinterpret_cast<const float4*>(ap);
            av1 = *reinterpret_cast<const float4*>(ap + 4);
        }
        As[acolg + 0][arow] = f2tf32(av0.x);
        As[acolg + 1][arow] = f2tf32(av0.y);
        As[acolg + 2][arow] = f2tf32(av0.z);
        As[acolg + 3][arow] = f2tf32(av0.w);
        As[acolg + 4][arow] = f2tf32(av1.x);
        As[acolg + 5][arow] = f2tf32(av1.y);
        As[acolg + 6][arow] = f2tf32(av1.z);
        As[acolg + 7][arow] = f2tf32(av1.w);

        // ---- load B tile (16 x 128) ----
#pragma unroll
        for (int t = tid; t < 512; t += 256) {
            int r  = t >> 5;            // k row 0..15
            int c4 = (t & 31) * 4;      // col group
            float4 bv = make_float4(0.f, 0.f, 0.f, 0.f);
            if (bn + c4 + 3 < N)
                bv = *reinterpret_cast<const float4*>(&B[(long)(k0 + r) * N + bn + c4]);
            Bs[r][c4 + 0] = f2tf32(bv.x);
            Bs[r][c4 + 1] = f2tf32(bv.y);
            Bs[r][c4 + 2] = f2tf32(bv.z);
            Bs[r][c4 + 3] = f2tf32(bv.w);
        }
        __syncthreads();

#pragma unroll
        for (int ks = 0; ks < 16; ks += 8) {
            unsigned af[4][4], bf[4][2];
#pragma unroll
            for (int mi = 0; mi < 4; mi++) {
                int mrow = wm * 64 + mi * 16 + gid;
                af[mi][0] = As[ks + tig][mrow];
                af[mi][1] = As[ks + tig][mrow + 8];
                af[mi][2] = As[ks + tig + 4][mrow];
                af[mi][3] = As[ks + tig + 4][mrow + 8];
            }
#pragma unroll
            for (int nj = 0; nj < 4; nj++) {
                int ncol = wn * 32 + nj * 8 + gid;
                bf[nj][0] = Bs[ks + tig][ncol];
                bf[nj][1] = Bs[ks + tig + 4][ncol];
            }
#pragma unroll
            for (int mi = 0; mi < 4; mi++)
#pragma unroll
                for (int nj = 0; nj < 4; nj++) {
                    asm volatile(
                        "mma.sync.aligned.m16n8k8.row.col.f32.tf32.tf32.f32 "
                        "{%0,%1,%2,%3}, {%4,%5,%6,%7}, {%8,%9}, {%0,%1,%2,%3};"
                        : "+f"(acc[mi][nj][0]), "+f"(acc[mi][nj][1]),
                          "+f"(acc[mi][nj][2]), "+f"(acc[mi][nj][3])
                        : "r"(af[mi][0]), "r"(af[mi][1]), "r"(af[mi][2]), "r"(af[mi][3]),
                          "r"(bf[nj][0]), "r"(bf[nj][1]));
                }
        }
        __syncthreads();
    }

    // ---- epilogue ----
#pragma unroll
    for (int mi = 0; mi < 4; mi++) {
        int m0 = bm + wm * 64 + mi * 16 + gid;
#pragma unroll
        for (int nj = 0; nj < 4; nj++) {
            int n0 = bn + wn * 32 + nj * 8 + tig * 2;
            if (n0 < N) {
                float b0 = bias ? bias[n0]     : 0.f;
                float b1 = bias ? bias[n0 + 1] : 0.f;
                if (m0 < M) {
                    C[(long)m0 * N + n0]     = acc[mi][nj][0] + b0;
                    C[(long)m0 * N + n0 + 1] = acc[mi][nj][1] + b1;
                }
                if (m0 + 8 < M) {
                    C[(long)(m0 + 8) * N + n0]     = acc[mi][nj][2] + b0;
                    C[(long)(m0 + 8) * N + n0 + 1] = acc[mi][nj][3] + b1;
                }
            }
        }
    }
}

// el/er per (relation, node): one warp per (r,n), coalesced z reads + shfl reduce
__global__ void k_attn_dot(const float* __restrict__ al,
                           const float* __restrict__ ar) {
    long gw = ((long)blockIdx.x * blockDim.x + threadIdx.x) >> 5;
    int lane = threadIdx.x & 31;
    if (gw >= (long)R_TOTAL * N_NODES) return;
    int r = (int)(gw / N_NODES);
    const float* zp = g_z + gw * DIM_OUT;
#pragma unroll
    for (int h = 0; h < HEADS; h++) {
        float zv = zp[h * 32 + lane];
        float sl = zv * al[(r * HEADS + h) * DHEAD + lane];
        float sr = zv * ar[(r * HEADS + h) * DHEAD + lane];
#pragma unroll
        for (int o = 16; o; o >>= 1) {
            sl += __shfl_xor_sync(0xFFFFFFFFu, sl, o);
            sr += __shfl_xor_sync(0xFFFFFFFFu, sr, o);
        }
        if (lane == 0) {
            g_el[gw * HEADS + h] = sl;
            g_er[gw * HEADS + h] = sr;
        }
    }
}

__device__ __forceinline__ float edge_e(int r, int e, int h,
                                        const int* __restrict__ src,
                                        const int* __restrict__ dst,
                                        int* s_out, int* d_out_) {
    int s = src[r * N_EDGES + e];
    int d = dst[r * N_EDGES + e];
    *s_out = s; *d_out_ = d;
    float ev = g_el[((long)r * N_NODES + s) * HEADS + h] +
               g_er[((long)r * N_NODES + d) * HEADS + h];
    return (ev >= 0.f) ? ev : NEG_SLOPE * ev;
}

__global__ void k_edge_max(const int* __restrict__ src, const int* __restrict__ dst) {
    long i = (long)blockIdx.x * blockDim.x + threadIdx.x;
    if (i >= (long)R_TOTAL * N_EDGES * HEADS) return;
    int h = (int)(i % HEADS);
    int e = (int)((i / HEADS) % N_EDGES);
    int r = (int)(i / ((long)HEADS * N_EDGES));
    int s, d;
    float ev = edge_e(r, e, h, src, dst, &s, &d);
    atomicMax(&g_menc[((long)r * N_NODES + d) * HEADS + h], fenc(ev));
}

__global__ void k_edge_ex(const int* __restrict__ src, const int* __restrict__ dst) {
    long i = (long)blockIdx.x * blockDim.x + threadIdx.x;
    if (i >= (long)R_TOTAL * N_EDGES * HEADS) return;
    int h = (int)(i % HEADS);
    int e = (int)((i / HEADS) % N_EDGES);
    int r = (int)(i / ((long)HEADS * N_EDGES));
    int s, d;
    float ev = edge_e(r, e, h, src, dst, &s, &d);
    float m = fdec(g_menc[((long)r * N_NODES + d) * HEADS + h]);
    float ex = expf(ev - m);
    g_ex[i] = ex;
    atomicAdd(&g_den[((long)r * N_NODES + d) * HEADS + h], ex);
}

// message + scatter, alpha normalization fused (reads den directly)
__global__ void k_msg(const int* __restrict__ src, const int* __restrict__ dst) {
    long i = (long)blockIdx.x * blockDim.x + threadIdx.x;
    if (i >= (long)R_TOTAL * N_EDGES * DIM_OUT) return;
    int c = (int)(i & 127);
    int e = (int)((i >> 7) % N_EDGES);
    int r = (int)(i / ((long)N_EDGES * DIM_OUT));
    int h = c >> 5;
    int s = src[r * N_EDGES + e];
    int d = dst[r * N_EDGES + e];
    float ex = g_ex[((long)r * N_EDGES + e) * HEADS + h];
    float den = fmaxf(g_den[((long)r * N_NODES + d) * HEADS + h], 1e-9f);
    float v = (ex / den) * g_z[((long)r * N_NODES + s) * DIM_OUT + c];
    atomicAdd(&g_acc[(long)d * DIM_OUT + c], v);
}

__global__ void k_finalize() {
    long i = (long)blockIdx.x * blockDim.x + threadIdx.x;
    if (i >= (long)N_NODES * DIM_OUT) return;
    int n = (int)(i / DIM_OUT);
    int c = (int)(i % DIM_OUT);
    float v = g_acc[i] * (1.0f / (float)R_TOTAL);
    g_x[(long)n * DIN + c] = (v > 0.f) ? v : 0.f;
}

__global__ void k_buildA(const int* __restrict__ root_idx,
                         const int* __restrict__ rel,
                         const float* __restrict__ sub_rel_emb,
                         const float* __restrict__ obj_rel_emb) {
    long i = (long)blockIdx.x * blockDim.x + threadIdx.x;
    if (i >= (long)2 * BATCH * KCLS) return;
    int b = (int)(i / KCLS);
    int c = (int)(i % KCLS);
    if (b < BATCH) {
        if (c < DIM_OUT) g_A[i] = g_x[(long)root_idx[BATCH + b] * DIN + c];
        else             g_A[i] = obj_rel_emb[rel[b] * DIM_R + (c - DIM_OUT)];
    } else {
        int bb = b - BATCH;
        if (c < DIM_OUT) g_A[i] = g_x[(long)root_idx[bb] * DIN + c];
        else             g_A[i] = sub_rel_emb[rel[bb] * DIM_R + (c - DIM_OUT)];
    }
}

// ---------------- launch ----------------
extern "C" void kernel_launch(void* const* d_in, const int* in_sizes, int n_in,
                              void* d_out, int out_size) {
    const int*   node_ids    = (const int*)d_in[0];
    const int*   edge_src    = (const int*)d_in[1];
    const int*   edge_dst    = (const int*)d_in[2];
    const int*   root_idx    = (const int*)d_in[3];
    const int*   rel         = (const int*)d_in[4];
    const float* entity_emb  = (const float*)d_in[5];
    const float* basis_freq  = (const float*)d_in[6];
    const float* phase       = (const float*)d_in[7];
    const float* fc_w        = (const float*)d_in[8];
    const float* attn_l      = (const float*)d_in[9];
    const float* attn_r      = (const float*)d_in[10];
    const float* sub_rel_emb = (const float*)d_in[11];
    const float* obj_rel_emb = (const float*)d_in[12];
    const float* sub_cls_w   = (const float*)d_in[13];
    const float* sub_cls_b   = (const float*)d_in[14];
    const float* obj_cls_w   = (const float*)d_in[15];
    const float* obj_cls_b   = (const float*)d_in[16];
    const int*   ts_ptr      = (n_in > 17) ? (const int*)d_in[17] : nullptr;

    float* out = (float*)d_out;

    float* px; float* pz; float* pA;
    cudaGetSymbolAddress((void**)&px, g_x);
    cudaGetSymbolAddress((void**)&pz, g_z);
    cudaGetSymbolAddress((void**)&pA, g_A);

    const int TB = 256;
    long n_init = (long)N_NODES * DIN;
    k_init<<<(unsigned)((n_init + TB - 1) / TB), TB>>>(node_ids, entity_emb, basis_freq, phase, ts_ptr);

    const long n_warps    = (long)R_TOTAL * N_NODES;           // attn_dot: 1 warp each
    const long n_edgehead = (long)R_TOTAL * N_EDGES * HEADS;
    const long n_zero     = (long)N_NODES * DIM_OUT;
    const long n_msg      = (long)R_TOTAL * N_EDGES * DIM_OUT;

    for (int l = 0; l < 2; l++) {
        k_zero<<<(unsigned)((n_zero + TB - 1) / TB), TB>>>();

        // z[r] = x @ fc_w[l][r]   for all 17 relations (tensor cores, tf32)
        dim3 gz(1, (N_NODES + 127) / 128, R_TOTAL);
        tfgemm<<<gz, 256>>>(px, 0,
                            fc_w + (long)l * R_TOTAL * DIN * DIM_OUT, (long)DIN * DIM_OUT,
                            pz, (long)N_NODES * DIM_OUT,
                            nullptr, N_NODES, DIM_OUT, DIN);

        k_attn_dot<<<(unsigned)((n_warps * 32 + TB - 1) / TB), TB>>>(
            attn_l + (long)l * R_TOTAL * HEADS * DHEAD,
            attn_r + (long)l * R_TOTAL * HEADS * DHEAD);

        k_edge_max<<<(unsigned)((n_edgehead + TB - 1) / TB), TB>>>(edge_src, edge_dst);
        k_edge_ex<<<(unsigned)((n_edgehead + TB - 1) / TB), TB>>>(edge_src, edge_dst);
        k_msg<<<(unsigned)((n_msg + TB - 1) / TB), TB>>>(edge_src, edge_dst);

        k_finalize<<<(unsigned)((n_zero + TB - 1) / TB), TB>>>();
    }

    long n_bA = (long)2 * BATCH * KCLS;
    k_buildA<<<(unsigned)((n_bA + TB - 1) / TB), TB>>>(root_idx, rel, sub_rel_emb, obj_rel_emb);

    dim3 gc((NUME + 127) / 128, (BATCH + 127) / 128, 1);
    // sub_pred = A_sub @ sub_cls_w + sub_cls_b   (tensor cores, tf32)
    tfgemm<<<gc, 256>>>(pA, 0, sub_cls_w, 0, out, 0,
                        sub_cls_b, BATCH, NUME, KCLS);
    // obj_pred = A_obj @ obj_cls_w + obj_cls_b
    tfgemm<<<gc, 256>>>(pA + (long)BATCH * KCLS, 0, obj_cls_w, 0,
                        out + (long)BATCH * NUME, 0,
                        obj_cls_b, BATCH, NUME, KCLS);
    (void)in_sizes; (void)out_size;
}

// round 5
// speedup vs baseline: 2.5170x; 1.5521x over previous
#include <cuda_runtime.h>
#include <math.h>

#define NUME     30000
#define NUMR     8
#define DIM_IN   128
#define DIM_OUT  128
#define DIM_R    64
#define DIM_T    32
#define HEADS    4
#define DHEAD    32
#define R_TOTAL  17
#define N_NODES  20000
#define N_EDGES  15000
#define BATCH    1024
#define DIN      160
#define KCLS     (DIM_OUT + DIM_R)   // 192
#define NEG_SLOPE 0.2f

// ---------------- scratch (device globals; no allocation allowed) ----------------
__device__ __align__(16) float    g_x[N_NODES * DIN];
__device__ __align__(16) float    g_z[(size_t)R_TOTAL * N_NODES * DIM_OUT];
__device__ __align__(16) float    g_el[R_TOTAL * N_NODES * HEADS];
__device__ __align__(16) float    g_er[R_TOTAL * N_NODES * HEADS];
__device__ __align__(16) unsigned g_menc[R_TOTAL * N_NODES * HEADS];
__device__ __align__(16) float    g_den[R_TOTAL * N_NODES * HEADS];
__device__ __align__(16) float    g_ex[R_TOTAL * N_EDGES * HEADS];
__device__ __align__(16) float    g_acc[N_NODES * DIM_OUT];
__device__ __align__(16) float    g_A[2 * BATCH * KCLS];

__device__ __forceinline__ unsigned fenc(float f) {
    unsigned u = __float_as_uint(f);
    return (u & 0x80000000u) ? ~u : (u | 0x80000000u);
}
__device__ __forceinline__ float fdec(unsigned u) {
    return (u & 0x80000000u) ? __uint_as_float(u & 0x7FFFFFFFu) : __uint_as_float(~u);
}
__device__ __forceinline__ unsigned f2tf32(float f) {
    unsigned r;
    asm("cvt.rna.tf32.f32 %0, %1;" : "=r"(r) : "f"(f));
    return r;
}

// ---------------- kernels ----------------

__global__ void k_init(const int* __restrict__ node_ids,
                       const float* __restrict__ entity_emb,
                       const float* __restrict__ basis_freq,
                       const float* __restrict__ phase,
                       const int* __restrict__ ts_ptr) {
    long i = (long)blockIdx.x * blockDim.x + threadIdx.x;
    if (i >= (long)N_NODES * DIN) return;
    int n = (int)(i / DIN);
    int c = (int)(i % DIN);
    int nid = node_ids[n];
    if (c < DIM_IN) {
        g_x[i] = entity_emb[(long)(nid % NUME) * DIM_IN + c];
    } else {
        int ts = ts_ptr ? ts_ptr[0] : 31;
        float dt = (float)(ts - 1 - nid / NUME);
        int t = c - DIM_IN;
        g_x[i] = cosf(dt * basis_freq[t] + phase[t]);
    }
}

__global__ void k_zero() {
    long i = (long)blockIdx.x * blockDim.x + threadIdx.x;
    const long NA = (long)R_TOTAL * N_NODES * HEADS;
    const long NB = (long)N_NODES * DIM_OUT;
    if (i < NA) { g_menc[i] = 0u; g_den[i] = 0.0f; }
    if (i < NB) { g_acc[i] = 0.0f; }
}

// ---------------- tf32 tensor-core GEMM (register-prefetch pipelined) ----------------
// C[z] (M x N) = A[z] (M x K, row-major) @ B[z] (K x N, row-major) (+ bias)
// If al != nullptr: additionally computes el/er = head-wise dot of C rows with
// attn vectors (requires N == 128, bn == 0, each warp's 32 cols == one head).
__global__ __launch_bounds__(256) void tfgemm(
    const float* __restrict__ Aall, long sA,
    const float* __restrict__ Ball, long sB,
    float* __restrict__ Call, long sC,
    const float* __restrict__ bias,
    int M, int N, int K,
    const float* __restrict__ al, const float* __restrict__ ar,
    float* __restrict__ el, float* __restrict__ er) {
    const float* A = Aall + sA * blockIdx.z;
    const float* B = Ball + sB * blockIdx.z;
    float* C = Call + sC * blockIdx.z;
    const int bm = blockIdx.y * 128;
    const int bn = blockIdx.x * 128;
    const int tid  = threadIdx.x;
    const int warp = tid >> 5;
    const int lane = tid & 31;
    const int wm = warp & 1;
    const int wn = warp >> 1;
    const int gid = lane >> 2;
    const int tig = lane & 3;

    __shared__ unsigned As[16][136];
    __shared__ unsigned Bs[16][136];

    float acc[4][4][4];
#pragma unroll
    for (int i = 0; i < 4; i++)
#pragma unroll
        for (int j = 0; j < 4; j++)
#pragma unroll
            for (int q = 0; q < 4; q++) acc[i][j][q] = 0.0f;

    const int arow  = tid >> 1;
    const int acolg = (tid & 1) * 8;
    const bool avalid = (bm + arow) < M;
    const int brow0 = tid >> 5;            // B load rows: brow0, brow0+8
    const int bcol4 = (tid & 31) * 4;
    const bool bvalid = (bn + bcol4 + 3) < N;

    float4 av0, av1, bv0, bv1;

    // prefetch first tile
    {
        av0 = make_float4(0.f,0.f,0.f,0.f); av1 = av0; bv0 = av0; bv1 = av0;
        if (avalid) {
            const float* ap = &A[(long)(bm + arow) * K + acolg];
            av0 = *reinterpret_cast<const float4*>(ap);
            av1 = *reinterpret_cast<const float4*>(ap + 4);
        }
        if (bvalid) {
            bv0 = *reinterpret_cast<const float4*>(&B[(long)brow0 * N + bn + bcol4]);
            bv1 = *reinterpret_cast<const float4*>(&B[(long)(brow0 + 8) * N + bn + bcol4]);
        }
    }

    for (int k0 = 0; k0 < K; k0 += 16) {
        // store current tile to smem (convert to tf32)
        As[acolg + 0][arow] = f2tf32(av0.x);
        As[acolg + 1][arow] = f2tf32(av0.y);
        As[acolg + 2][arow] = f2tf32(av0.z);
        As[acolg + 3][arow] = f2tf32(av0.w);
        As[acolg + 4][arow] = f2tf32(av1.x);
        As[acolg + 5][arow] = f2tf32(av1.y);
        As[acolg + 6][arow] = f2tf32(av1.z);
        As[acolg + 7][arow] = f2tf32(av1.w);
        Bs[brow0][bcol4 + 0] = f2tf32(bv0.x);
        Bs[brow0][bcol4 + 1] = f2tf32(bv0.y);
        Bs[brow0][bcol4 + 2] = f2tf32(bv0.z);
        Bs[brow0][bcol4 + 3] = f2tf32(bv0.w);
        Bs[brow0 + 8][bcol4 + 0] = f2tf32(bv1.x);
        Bs[brow0 + 8][bcol4 + 1] = f2tf32(bv1.y);
        Bs[brow0 + 8][bcol4 + 2] = f2tf32(bv1.z);
        Bs[brow0 + 8][bcol4 + 3] = f2tf32(bv1.w);
        __syncthreads();

        // prefetch next tile (LDG overlapped with MMA below)
        int kn = k0 + 16;
        if (kn < K) {
            av0 = make_float4(0.f,0.f,0.f,0.f); av1 = av0; bv0 = av0; bv1 = av0;
            if (avalid) {
                const float* ap = &A[(long)(bm + arow) * K + kn + acolg];
                av0 = *reinterpret_cast<const float4*>(ap);
                av1 = *reinterpret_cast<const float4*>(ap + 4);
            }
            if (bvalid) {
                bv0 = *reinterpret_cast<const float4*>(&B[(long)(kn + brow0) * N + bn + bcol4]);
                bv1 = *reinterpret_cast<const float4*>(&B[(long)(kn + brow0 + 8) * N + bn + bcol4]);
            }
        }

#pragma unroll
        for (int ks = 0; ks < 16; ks += 8) {
            unsigned af[4][4], bf[4][2];
#pragma unroll
            for (int mi = 0; mi < 4; mi++) {
                int mrow = wm * 64 + mi * 16 + gid;
                af[mi][0] = As[ks + tig][mrow];
                af[mi][1] = As[ks + tig][mrow + 8];
                af[mi][2] = As[ks + tig + 4][mrow];
                af[mi][3] = As[ks + tig + 4][mrow + 8];
            }
#pragma unroll
            for (int nj = 0; nj < 4; nj++) {
                int ncol = wn * 32 + nj * 8 + gid;
                bf[nj][0] = Bs[ks + tig][ncol];
                bf[nj][1] = Bs[ks + tig + 4][ncol];
            }
#pragma unroll
            for (int mi = 0; mi < 4; mi++)
#pragma unroll
                for (int nj = 0; nj < 4; nj++) {
                    asm volatile(
                        "mma.sync.aligned.m16n8k8.row.col.f32.tf32.tf32.f32 "
                        "{%0,%1,%2,%3}, {%4,%5,%6,%7}, {%8,%9}, {%0,%1,%2,%3};"
                        : "+f"(acc[mi][nj][0]), "+f"(acc[mi][nj][1]),
                          "+f"(acc[mi][nj][2]), "+f"(acc[mi][nj][3])
                        : "r"(af[mi][0]), "r"(af[mi][1]), "r"(af[mi][2]), "r"(af[mi][3]),
                          "r"(bf[nj][0]), "r"(bf[nj][1]));
                }
        }
        __syncthreads();
    }

    // ---- epilogue: store C ----
#pragma unroll
    for (int mi = 0; mi < 4; mi++) {
        int m0 = bm + wm * 64 + mi * 16 + gid;
#pragma unroll
        for (int nj = 0; nj < 4; nj++) {
            int n0 = bn + wn * 32 + nj * 8 + tig * 2;
            if (n0 < N) {
                float b0 = bias ? bias[n0]     : 0.f;
                float b1 = bias ? bias[n0 + 1] : 0.f;
                if (m0 < M) {
                    C[(long)m0 * N + n0]     = acc[mi][nj][0] + b0;
                    C[(long)m0 * N + n0 + 1] = acc[mi][nj][1] + b1;
                }
                if (m0 + 8 < M) {
                    C[(long)(m0 + 8) * N + n0]     = acc[mi][nj][2] + b0;
                    C[(long)(m0 + 8) * N + n0 + 1] = acc[mi][nj][3] + b1;
                }
            }
        }
    }

    // ---- fused attention dots: el/er per (node, head=wn) ----
    if (al) {
        const float* alp = al + (long)blockIdx.z * HEADS * DHEAD + wn * DHEAD;
        const float* arp = ar + (long)blockIdx.z * HEADS * DHEAD + wn * DHEAD;
#pragma unroll
        for (int mi = 0; mi < 4; mi++) {
            float sl0 = 0.f, sr0 = 0.f, sl1 = 0.f, sr1 = 0.f;
#pragma unroll
            for (int nj = 0; nj < 4; nj++) {
                int dh = nj * 8 + tig * 2;
                float w0 = alp[dh], w1 = alp[dh + 1];
                float v0 = arp[dh], v1 = arp[dh + 1];
                sl0 += acc[mi][nj][0] * w0 + acc[mi][nj][1] * w1;
                sr0 += acc[mi][nj][0] * v0 + acc[mi][nj][1] * v1;
                sl1 += acc[mi][nj][2] * w0 + acc[mi][nj][3] * w1;
                sr1 += acc[mi][nj][2] * v0 + acc[mi][nj][3] * v1;
            }
#pragma unroll
            for (int o = 1; o <= 2; o <<= 1) {
                sl0 += __shfl_xor_sync(0xFFFFFFFFu, sl0, o);
                sr0 += __shfl_xor_sync(0xFFFFFFFFu, sr0, o);
                sl1 += __shfl_xor_sync(0xFFFFFFFFu, sl1, o);
                sr1 += __shfl_xor_sync(0xFFFFFFFFu, sr1, o);
            }
            if (tig == 0) {
                int m0 = bm + wm * 64 + mi * 16 + gid;
                long base = (long)blockIdx.z * N_NODES;
                if (m0 < M) {
                    el[(base + m0) * HEADS + wn] = sl0;
                    er[(base + m0) * HEADS + wn] = sr0;
                }
                if (m0 + 8 < M) {
                    el[(base + m0 + 8) * HEADS + wn] = sl1;
                    er[(base + m0 + 8) * HEADS + wn] = sr1;
                }
            }
        }
    }
}

__device__ __forceinline__ float edge_e(int r, int e, int h,
                                        const int* __restrict__ src,
                                        const int* __restrict__ dst,
                                        int* s_out, int* d_out_) {
    int s = src[r * N_EDGES + e];
    int d = dst[r * N_EDGES + e];
    *s_out = s; *d_out_ = d;
    float ev = g_el[((long)r * N_NODES + s) * HEADS + h] +
               g_er[((long)r * N_NODES + d) * HEADS + h];
    return (ev >= 0.f) ? ev : NEG_SLOPE * ev;
}

__global__ void k_edge_max(const int* __restrict__ src, const int* __restrict__ dst) {
    long i = (long)blockIdx.x * blockDim.x + threadIdx.x;
    if (i >= (long)R_TOTAL * N_EDGES * HEADS) return;
    int h = (int)(i % HEADS);
    int e = (int)((i / HEADS) % N_EDGES);
    int r = (int)(i / ((long)HEADS * N_EDGES));
    int s, d;
    float ev = edge_e(r, e, h, src, dst, &s, &d);
    atomicMax(&g_menc[((long)r * N_NODES + d) * HEADS + h], fenc(ev));
}

__global__ void k_edge_ex(const int* __restrict__ src, const int* __restrict__ dst) {
    long i = (long)blockIdx.x * blockDim.x + threadIdx.x;
    if (i >= (long)R_TOTAL * N_EDGES * HEADS) return;
    int h = (int)(i % HEADS);
    int e = (int)((i / HEADS) % N_EDGES);
    int r = (int)(i / ((long)HEADS * N_EDGES));
    int s, d;
    float ev = edge_e(r, e, h, src, dst, &s, &d);
    float m = fdec(g_menc[((long)r * N_NODES + d) * HEADS + h]);
    float ex = expf(ev - m);
    g_ex[i] = ex;
    atomicAdd(&g_den[((long)r * N_NODES + d) * HEADS + h], ex);
}

// warp-per-edge message scatter: float4 z reads + red.global.add.v4
__global__ void k_msg(const int* __restrict__ src, const int* __restrict__ dst) {
    long gw = ((long)blockIdx.x * blockDim.x + threadIdx.x) >> 5;
    int lane = threadIdx.x & 31;
    if (gw >= (long)R_TOTAL * N_EDGES) return;
    int r = (int)(gw / N_EDGES);
    int e = (int)(gw % N_EDGES);
    int s = src[r * N_EDGES + e];
    int d = dst[r * N_EDGES + e];
    int c0 = lane * 4;
    int h = lane >> 3;
    float ex  = g_ex[gw * HEADS + h];
    float den = fmaxf(g_den[((long)r * N_NODES + d) * HEADS + h], 1e-9f);
    float a = ex / den;
    float4 zv = *reinterpret_cast<const float4*>(&g_z[((long)r * N_NODES + s) * DIM_OUT + c0]);
    float* p = &g_acc[(long)d * DIM_OUT + c0];
    asm volatile("red.global.add.v4.f32 [%0], {%1,%2,%3,%4};"
                 :: "l"(p), "f"(a * zv.x), "f"(a * zv.y), "f"(a * zv.z), "f"(a * zv.w)
                 : "memory");
}

__global__ void k_finalize() {
    long i = (long)blockIdx.x * blockDim.x + threadIdx.x;
    if (i >= (long)N_NODES * DIM_OUT) return;
    int n = (int)(i / DIM_OUT);
    int c = (int)(i % DIM_OUT);
    float v = g_acc[i] * (1.0f / (float)R_TOTAL);
    g_x[(long)n * DIN + c] = (v > 0.f) ? v : 0.f;
}

__global__ void k_buildA(const int* __restrict__ root_idx,
                         const int* __restrict__ rel,
                         const float* __restrict__ sub_rel_emb,
                         const float* __restrict__ obj_rel_emb) {
    long i = (long)blockIdx.x * blockDim.x + threadIdx.x;
    if (i >= (long)2 * BATCH * KCLS) return;
    int b = (int)(i / KCLS);
    int c = (int)(i % KCLS);
    if (b < BATCH) {
        if (c < DIM_OUT) g_A[i] = g_x[(long)root_idx[BATCH + b] * DIN + c];
        else             g_A[i] = obj_rel_emb[rel[b] * DIM_R + (c - DIM_OUT)];
    } else {
        int bb = b - BATCH;
        if (c < DIM_OUT) g_A[i] = g_x[(long)root_idx[bb] * DIN + c];
        else             g_A[i] = sub_rel_emb[rel[bb] * DIM_R + (c - DIM_OUT)];
    }
}

// ---------------- launch ----------------
extern "C" void kernel_launch(void* const* d_in, const int* in_sizes, int n_in,
                              void* d_out, int out_size) {
    const int*   node_ids    = (const int*)d_in[0];
    const int*   edge_src    = (const int*)d_in[1];
    const int*   edge_dst    = (const int*)d_in[2];
    const int*   root_idx    = (const int*)d_in[3];
    const int*   rel         = (const int*)d_in[4];
    const float* entity_emb  = (const float*)d_in[5];
    const float* basis_freq  = (const float*)d_in[6];
    const float* phase       = (const float*)d_in[7];
    const float* fc_w        = (const float*)d_in[8];
    const float* attn_l      = (const float*)d_in[9];
    const float* attn_r      = (const float*)d_in[10];
    const float* sub_rel_emb = (const float*)d_in[11];
    const float* obj_rel_emb = (const float*)d_in[12];
    const float* sub_cls_w   = (const float*)d_in[13];
    const float* sub_cls_b   = (const float*)d_in[14];
    const float* obj_cls_w   = (const float*)d_in[15];
    const float* obj_cls_b   = (const float*)d_in[16];
    const int*   ts_ptr      = (n_in > 17) ? (const int*)d_in[17] : nullptr;

    float* out = (float*)d_out;

    float* px; float* pz; float* pA; float* pel; float* per;
    cudaGetSymbolAddress((void**)&px, g_x);
    cudaGetSymbolAddress((void**)&pz, g_z);
    cudaGetSymbolAddress((void**)&pA, g_A);
    cudaGetSymbolAddress((void**)&pel, g_el);
    cudaGetSymbolAddress((void**)&per, g_er);

    const int TB = 256;
    long n_init = (long)N_NODES * DIN;
    k_init<<<(unsigned)((n_init + TB - 1) / TB), TB>>>(node_ids, entity_emb, basis_freq, phase, ts_ptr);

    const long n_edgehead = (long)R_TOTAL * N_EDGES * HEADS;
    const long n_zero     = (long)N_NODES * DIM_OUT;
    const long n_msgw     = (long)R_TOTAL * N_EDGES * 32;   // warp per edge

    for (int l = 0; l < 2; l++) {
        k_zero<<<(unsigned)((n_zero + TB - 1) / TB), TB>>>();

        // z[r] = x @ fc_w[l][r] with fused el/er epilogue (tensor cores, tf32)
        dim3 gz(1, (N_NODES + 127) / 128, R_TOTAL);
        tfgemm<<<gz, 256>>>(px, 0,
                            fc_w + (long)l * R_TOTAL * DIN * DIM_OUT, (long)DIN * DIM_OUT,
                            pz, (long)N_NODES * DIM_OUT,
                            nullptr, N_NODES, DIM_OUT, DIN,
                            attn_l + (long)l * R_TOTAL * HEADS * DHEAD,
                            attn_r + (long)l * R_TOTAL * HEADS * DHEAD,
                            pel, per);

        k_edge_max<<<(unsigned)((n_edgehead + TB - 1) / TB), TB>>>(edge_src, edge_dst);
        k_edge_ex<<<(unsigned)((n_edgehead + TB - 1) / TB), TB>>>(edge_src, edge_dst);
        k_msg<<<(unsigned)((n_msgw + TB - 1) / TB), TB>>>(edge_src, edge_dst);

        k_finalize<<<(unsigned)((n_zero + TB - 1) / TB), TB>>>();
    }

    long n_bA = (long)2 * BATCH * KCLS;
    k_buildA<<<(unsigned)((n_bA + TB - 1) / TB), TB>>>(root_idx, rel, sub_rel_emb, obj_rel_emb);

    dim3 gc((NUME + 127) / 128, (BATCH + 127) / 128, 1);
    tfgemm<<<gc, 256>>>(pA, 0, sub_cls_w, 0, out, 0,
                        sub_cls_b, BATCH, NUME, KCLS,
                        nullptr, nullptr, nullptr, nullptr);
    tfgemm<<<gc, 256>>>(pA + (long)BATCH * KCLS, 0, obj_cls_w, 0,
                        out + (long)BATCH * NUME, 0,
                        obj_cls_b, BATCH, NUME, KCLS,
                        nullptr, nullptr, nullptr, nullptr);
    (void)in_sizes; (void)out_size;
}

// round 7
// speedup vs baseline: 2.8560x; 1.1347x over previous
#include <cuda_runtime.h>
#include <math.h>
#include <stdint.h>

#define NUME     30000
#define NUMR     8
#define DIM_IN   128
#define DIM_OUT  128
#define DIM_R    64
#define DIM_T    32
#define HEADS    4
#define DHEAD    32
#define R_TOTAL  17
#define N_NODES  20000
#define N_EDGES  15000
#define BATCH    1024
#define DIN      160
#define KCLS     (DIM_OUT + DIM_R)   // 192
#define NEG_SLOPE 0.2f

#define NSTAGE   3
#define A_STRIDE 20                            // floats per A smem row (conflict-free)
#define B_STRIDE 136                           // floats per B smem row (conflict-free)
#define STAGE_FLOATS (128 * A_STRIDE + 16 * B_STRIDE)   // 2560 + 2176 = 4736
#define SMEM_GEMM (NSTAGE * STAGE_FLOATS * 4)           // 56832 B

// ---------------- scratch (device globals; no allocation allowed) ----------------
__device__ __align__(16) float    g_x[N_NODES * DIN];
__device__ __align__(16) float    g_z[(size_t)R_TOTAL * N_NODES * DIM_OUT];
__device__ __align__(16) float    g_el[R_TOTAL * N_NODES * HEADS];
__device__ __align__(16) float    g_er[R_TOTAL * N_NODES * HEADS];
__device__ __align__(16) unsigned g_menc[R_TOTAL * N_NODES * HEADS];
__device__ __align__(16) float    g_den[R_TOTAL * N_NODES * HEADS];
__device__ __align__(16) float    g_ex[R_TOTAL * N_EDGES * HEADS];
__device__ __align__(16) float    g_acc[N_NODES * DIM_OUT];
__device__ __align__(16) float    g_A[2 * BATCH * KCLS];

__device__ __forceinline__ unsigned fenc(float f) {
    unsigned u = __float_as_uint(f);
    return (u & 0x80000000u) ? ~u : (u | 0x80000000u);
}
__device__ __forceinline__ float fdec(unsigned u) {
    return (u & 0x80000000u) ? __uint_as_float(u & 0x7FFFFFFFu) : __uint_as_float(~u);
}
__device__ __forceinline__ unsigned f2tf32(float f) {
    unsigned r;
    asm("cvt.rna.tf32.f32 %0, %1;" : "=r"(r) : "f"(f));
    return r;
}
__device__ __forceinline__ unsigned smem_u32(const void* p) {
    unsigned a;
    asm("{ .reg .u64 t; cvta.to.shared.u64 t, %1; cvt.u32.u64 %0, t; }" : "=r"(a) : "l"(p));
    return a;
}

// ---------------- kernels ----------------

__global__ void k_init(const int* __restrict__ node_ids,
                       const float* __restrict__ entity_emb,
                       const float* __restrict__ basis_freq,
                       const float* __restrict__ phase,
                       const int* __restrict__ ts_ptr) {
    long i = (long)blockIdx.x * blockDim.x + threadIdx.x;
    if (i >= (long)N_NODES * DIN) return;
    int n = (int)(i / DIN);
    int c = (int)(i % DIN);
    int nid = node_ids[n];
    if (c < DIM_IN) {
        g_x[i] = entity_emb[(long)(nid % NUME) * DIM_IN + c];
    } else {
        int ts = ts_ptr ? ts_ptr[0] : 31;
        float dt = (float)(ts - 1 - nid / NUME);
        int t = c - DIM_IN;
        g_x[i] = cosf(dt * basis_freq[t] + phase[t]);
    }
}

__global__ void k_zero() {
    long i = (long)blockIdx.x * blockDim.x + threadIdx.x;
    const long NA = (long)R_TOTAL * N_NODES * HEADS;
    const long NB = (long)N_NODES * DIM_OUT;
    if (i < NA) { g_menc[i] = 0u; g_den[i] = 0.0f; }
    if (i < NB) { g_acc[i] = 0.0f; }
}

// ---------------- tf32 tensor-core GEMM, 3-stage cp.async pipeline ----------------
// C[z] (M x N) = A[z] (M x K, row-major) @ B[z] (K x N, row-major) (+ bias)
// If al != nullptr: fused el/er epilogue (requires N == 128, bn == 0).
// Requires K % 16 == 0, N % 4 == 0, M % 4 == 0 (A rows zfilled past M).
__global__ __launch_bounds__(256, 2) void tfgemm(
    const float* __restrict__ Aall, long sA,
    const float* __restrict__ Ball, long sB,
    float* __restrict__ Call, long sC,
    const float* __restrict__ bias,
    int M, int N, int K,
    const float* __restrict__ al, const float* __restrict__ ar,
    float* __restrict__ el, float* __restrict__ er) {
    extern __shared__ float smf[];
    const unsigned sbase = smem_u32(smf);
    const float* A = Aall + sA * blockIdx.z;
    const float* B = Ball + sB * blockIdx.z;
    float* C = Call + sC * blockIdx.z;
    const int bm = blockIdx.y * 128;
    const int bn = blockIdx.x * 128;
    const int tid  = threadIdx.x;
    const int warp = tid >> 5;
    const int lane = tid & 31;
    const int wm = warp & 1;       // 2 warps along M (64 each)
    const int wn = warp >> 1;      // 4 warps along N (32 each)
    const int gid = lane >> 2;     // 0..7
    const int tig = lane & 3;      // 0..3
    const int nchunks = K >> 4;

    float acc[4][4][4];
#pragma unroll
    for (int i = 0; i < 4; i++)
#pragma unroll
        for (int j = 0; j < 4; j++)
#pragma unroll
            for (int q = 0; q < 4; q++) acc[i][j][q] = 0.0f;

    // A load chunks: 128 rows x 4 x 16B ; B: 16 rows x 32 x 16B
    const int aq0 = tid, aq1 = tid + 256;
    const int arow0 = aq0 >> 2, ac0 = aq0 & 3;
    const int arow1 = aq1 >> 2, ac1 = aq1 & 3;
    const int brow0 = aq0 >> 5, bc0 = aq0 & 31;
    const int brow1 = aq1 >> 5, bc1 = aq1 & 31;

#define ISSUE_LOAD(chunk)                                                          \
    do {                                                                           \
        int _c = (chunk);                                                          \
        if (_c < nchunks) {                                                        \
            int _s = _c % NSTAGE;                                                  \
            unsigned _ab = sbase + (unsigned)(_s * STAGE_FLOATS) * 4u;             \
            unsigned _bb = _ab + 128u * A_STRIDE * 4u;                             \
            int _k0 = _c << 4;                                                     \
            {                                                                      \
                const float* _src = A + (long)(bm + arow0) * K + _k0 + ac0 * 4;    \
                unsigned _dst = _ab + (unsigned)(arow0 * A_STRIDE + ac0 * 4) * 4u; \
                unsigned _sz = (bm + arow0 < M) ? 16u : 0u;                        \
                asm volatile("cp.async.cg.shared.global [%0], [%1], 16, %2;"       \
                             :: "r"(_dst), "l"(_src), "r"(_sz));                   \
            }                                                                      \
            {                                                                      \
                const float* _src = A + (long)(bm + arow1) * K + _k0 + ac1 * 4;    \
                unsigned _dst = _ab + (unsigned)(arow1 * A_STRIDE + ac1 * 4) * 4u; \
                unsigned _sz = (bm + arow1 < M) ? 16u : 0u;                        \
                asm volatile("cp.async.cg.shared.global [%0], [%1], 16, %2;"       \
                             :: "r"(_dst), "l"(_src), "r"(_sz));                   \
            }                                                                      \
            {                                                                      \
                const float* _src = B + (long)(_k0 + brow0) * N + bn + bc0 * 4;    \
                unsigned _dst = _bb + (unsigned)(brow0 * B_STRIDE + bc0 * 4) * 4u; \
                unsigned _sz = (bn + bc0 * 4 + 3 < N) ? 16u : 0u;                  \
                asm volatile("cp.async.cg.shared.global [%0], [%1], 16, %2;"       \
                             :: "r"(_dst), "l"(_src), "r"(_sz));                   \
            }                                                                      \
            {                                                                      \
                const float* _src = B + (long)(_k0 + brow1) * N + bn + bc1 * 4;    \
                unsigned _dst = _bb + (unsigned)(brow1 * B_STRIDE + bc1 * 4) * 4u; \
                unsigned _sz = (bn + bc1 * 4 + 3 < N) ? 16u : 0u;                  \
                asm volatile("cp.async.cg.shared.global [%0], [%1], 16, %2;"       \
                             :: "r"(_dst), "l"(_src), "r"(_sz));                   \
            }                                                                      \
        }                                                                          \
        asm volatile("cp.async.commit_group;" ::: "memory");                       \
    } while (0)

    ISSUE_LOAD(0);
    ISSUE_LOAD(1);

    for (int c = 0; c < nchunks; c++) {
        asm volatile("cp.async.wait_group 1;" ::: "memory");
        __syncthreads();
        ISSUE_LOAD(c + 2);

        const float* Af = smf + (c % NSTAGE) * STAGE_FLOATS;
        const float* Bf = Af + 128 * A_STRIDE;
#pragma unroll
        for (int ks = 0; ks < 16; ks += 8) {
            unsigned af[4][4], bf[4][2];
#pragma unroll
            for (int mi = 0; mi < 4; mi++) {
                int mrow = wm * 64 + mi * 16 + gid;
                af[mi][0] = f2tf32(Af[mrow * A_STRIDE + ks + tig]);
                af[mi][1] = f2tf32(Af[(mrow + 8) * A_STRIDE + ks + tig]);
                af[mi][2] = f2tf32(Af[mrow * A_STRIDE + ks + tig + 4]);
                af[mi][3] = f2tf32(Af[(mrow + 8) * A_STRIDE + ks + tig + 4]);
            }
#pragma unroll
            for (int nj = 0; nj < 4; nj++) {
                int ncol = wn * 32 + nj * 8 + gid;
                bf[nj][0] = f2tf32(Bf[(ks + tig) * B_STRIDE + ncol]);
                bf[nj][1] = f2tf32(Bf[(ks + tig + 4) * B_STRIDE + ncol]);
            }
#pragma unroll
            for (int mi = 0; mi < 4; mi++)
#pragma unroll
                for (int nj = 0; nj < 4; nj++) {
                    asm volatile(
                        "mma.sync.aligned.m16n8k8.row.col.f32.tf32.tf32.f32 "
                        "{%0,%1,%2,%3}, {%4,%5,%6,%7}, {%8,%9}, {%0,%1,%2,%3};"
                        : "+f"(acc[mi][nj][0]), "+f"(acc[mi][nj][1]),
                          "+f"(acc[mi][nj][2]), "+f"(acc[mi][nj][3])
                        : "r"(af[mi][0]), "r"(af[mi][1]), "r"(af[mi][2]), "r"(af[mi][3]),
                          "r"(bf[nj][0]), "r"(bf[nj][1]));
                }
        }
    }

    // ---- epilogue: store C ----
#pragma unroll
    for (int mi = 0; mi < 4; mi++) {
        int m0 = bm + wm * 64 + mi * 16 + gid;
#pragma unroll
        for (int nj = 0; nj < 4; nj++) {
            int n0 = bn + wn * 32 + nj * 8 + tig * 2;
            if (n0 < N) {
                float b0 = bias ? bias[n0]     : 0.f;
                float b1 = bias ? bias[n0 + 1] : 0.f;
                if (m0 < M) {
                    C[(long)m0 * N + n0]     = acc[mi][nj][0] + b0;
                    C[(long)m0 * N + n0 + 1] = acc[mi][nj][1] + b1;
                }
                if (m0 + 8 < M) {
                    C[(long)(m0 + 8) * N + n0]     = acc[mi][nj][2] + b0;
                    C[(long)(m0 + 8) * N + n0 + 1] = acc[mi][nj][3] + b1;
                }
            }
        }
    }

    // ---- fused attention dots: el/er per (node, head=wn) ----
    if (al) {
        const float* alp = al + (long)blockIdx.z * HEADS * DHEAD + wn * DHEAD;
        const float* arp = ar + (long)blockIdx.z * HEADS * DHEAD + wn * DHEAD;
#pragma unroll
        for (int mi = 0; mi < 4; mi++) {
            float sl0 = 0.f, sr0 = 0.f, sl1 = 0.f, sr1 = 0.f;
#pragma unroll
            for (int nj = 0; nj < 4; nj++) {
                int dh = nj * 8 + tig * 2;
                float w0 = alp[dh], w1 = alp[dh + 1];
                float v0 = arp[dh], v1 = arp[dh + 1];
                sl0 += acc[mi][nj][0] * w0 + acc[mi][nj][1] * w1;
                sr0 += acc[mi][nj][0] * v0 + acc[mi][nj][1] * v1;
                sl1 += acc[mi][nj][2] * w0 + acc[mi][nj][3] * w1;
                sr1 += acc[mi][nj][2] * v0 + acc[mi][nj][3] * v1;
            }
#pragma unroll
            for (int o = 1; o <= 2; o <<= 1) {
                sl0 += __shfl_xor_sync(0xFFFFFFFFu, sl0, o);
                sr0 += __shfl_xor_sync(0xFFFFFFFFu, sr0, o);
                sl1 += __shfl_xor_sync(0xFFFFFFFFu, sl1, o);
                sr1 += __shfl_xor_sync(0xFFFFFFFFu, sr1, o);
            }
            if (tig == 0) {
                int m0 = bm + wm * 64 + mi * 16 + gid;
                long base = (long)blockIdx.z * N_NODES;
                if (m0 < M) {
                    el[(base + m0) * HEADS + wn] = sl0;
                    er[(base + m0) * HEADS + wn] = sr0;
                }
                if (m0 + 8 < M) {
                    el[(base + m0 + 8) * HEADS + wn] = sl1;
                    er[(base + m0 + 8) * HEADS + wn] = sr1;
                }
            }
        }
    }
}

__device__ __forceinline__ float edge_e(int r, int e, int h,
                                        const int* __restrict__ src,
                                        const int* __restrict__ dst,
                                        int* s_out, int* d_out_) {
    int s = src[r * N_EDGES + e];
    int d = dst[r * N_EDGES + e];
    *s_out = s; *d_out_ = d;
    float ev = g_el[((long)r * N_NODES + s) * HEADS + h] +
               g_er[((long)r * N_NODES + d) * HEADS + h];
    return (ev >= 0.f) ? ev : NEG_SLOPE * ev;
}

__global__ void k_edge_max(const int* __restrict__ src, const int* __restrict__ dst) {
    long i = (long)blockIdx.x * blockDim.x + threadIdx.x;
    if (i >= (long)R_TOTAL * N_EDGES * HEADS) return;
    int h = (int)(i % HEADS);
    int e = (int)((i / HEADS) % N_EDGES);
    int r = (int)(i / ((long)HEADS * N_EDGES));
    int s, d;
    float ev = edge_e(r, e, h, src, dst, &s, &d);
    atomicMax(&g_menc[((long)r * N_NODES + d) * HEADS + h], fenc(ev));
}

__global__ void k_edge_ex(const int* __restrict__ src, const int* __restrict__ dst) {
    long i = (long)blockIdx.x * blockDim.x + threadIdx.x;
    if (i >= (long)R_TOTAL * N_EDGES * HEADS) return;
    int h = (int)(i % HEADS);
    int e = (int)((i / HEADS) % N_EDGES);
    int r = (int)(i / ((long)HEADS * N_EDGES));
    int s, d;
    float ev = edge_e(r, e, h, src, dst, &s, &d);
    float m = fdec(g_menc[((long)r * N_NODES + d) * HEADS + h]);
    float ex = expf(ev - m);
    g_ex[i] = ex;
    atomicAdd(&g_den[((long)r * N_NODES + d) * HEADS + h], ex);
}

// warp-per-edge message scatter: float4 z reads + red.global.add.v4
__global__ void k_msg(const int* __restrict__ src, const int* __restrict__ dst) {
    long gw = ((long)blockIdx.x * blockDim.x + threadIdx.x) >> 5;
    int lane = threadIdx.x & 31;
    if (gw >= (long)R_TOTAL * N_EDGES) return;
    int r = (int)(gw / N_EDGES);
    int e = (int)(gw % N_EDGES);
    int s = src[r * N_EDGES + e];
    int d = dst[r * N_EDGES + e];
    int c0 = lane * 4;
    int h = lane >> 3;
    float ex  = g_ex[gw * HEADS + h];
    float den = fmaxf(g_den[((long)r * N_NODES + d) * HEADS + h], 1e-9f);
    float a = ex / den;
    float4 zv = *reinterpret_cast<const float4*>(&g_z[((long)r * N_NODES + s) * DIM_OUT + c0]);
    float* p = &g_acc[(long)d * DIM_OUT + c0];
    asm volatile("red.global.add.v4.f32 [%0], {%1,%2,%3,%4};"
                 :: "l"(p), "f"(a * zv.x), "f"(a * zv.y), "f"(a * zv.z), "f"(a * zv.w)
                 : "memory");
}

__global__ void k_finalize() {
    long i = (long)blockIdx.x * blockDim.x + threadIdx.x;
    if (i >= (long)N_NODES * DIM_OUT) return;
    int n = (int)(i / DIM_OUT);
    int c = (int)(i % DIM_OUT);
    float v = g_acc[i] * (1.0f / (float)R_TOTAL);
    g_x[(long)n * DIN + c] = (v > 0.f) ? v : 0.f;
}

__global__ void k_buildA(const int* __restrict__ root_idx,
                         const int* __restrict__ rel,
                         const float* __restrict__ sub_rel_emb,
                         const float* __restrict__ obj_rel_emb) {
    long i = (long)blockIdx.x * blockDim.x + threadIdx.x;
    if (i >= (long)2 * BATCH * KCLS) return;
    int b = (int)(i / KCLS);
    int c = (int)(i % KCLS);
    if (b < BATCH) {
        if (c < DIM_OUT) g_A[i] = g_x[(long)root_idx[BATCH + b] * DIN + c];
        else             g_A[i] = obj_rel_emb[rel[b] * DIM_R + (c - DIM_OUT)];
    } else {
        int bb = b - BATCH;
        if (c < DIM_OUT) g_A[i] = g_x[(long)root_idx[bb] * DIN + c];
        else             g_A[i] = sub_rel_emb[rel[bb] * DIM_R + (c - DIM_OUT)];
    }
}

// ---------------- launch ----------------
extern "C" void kernel_launch(void* const* d_in, const int* in_sizes, int n_in,
                              void* d_out, int out_size) {
    const int*   node_ids    = (const int*)d_in[0];
    const int*   edge_src    = (const int*)d_in[1];
    const int*   edge_dst    = (const int*)d_in[2];
    const int*   root_idx    = (const int*)d_in[3];
    const int*   rel         = (const int*)d_in[4];
    const float* entity_emb  = (const float*)d_in[5];
    const float* basis_freq  = (const float*)d_in[6];
    const float* phase       = (const float*)d_in[7];
    const float* fc_w        = (const float*)d_in[8];
    const float* attn_l      = (const float*)d_in[9];
    const float* attn_r      = (const float*)d_in[10];
    const float* sub_rel_emb = (const float*)d_in[11];
    const float* obj_rel_emb = (const float*)d_in[12];
    const float* sub_cls_w   = (const float*)d_in[13];
    const float* sub_cls_b   = (const float*)d_in[14];
    const float* obj_cls_w   = (const float*)d_in[15];
    const float* obj_cls_b   = (const float*)d_in[16];
    const int*   ts_ptr      = (n_in > 17) ? (const int*)d_in[17] : nullptr;

    float* out = (float*)d_out;

    float* px; float* pz; float* pA; float* pel; float* per;
    cudaGetSymbolAddress((void**)&px, g_x);
    cudaGetSymbolAddress((void**)&pz, g_z);
    cudaGetSymbolAddress((void**)&pA, g_A);
    cudaGetSymbolAddress((void**)&pel, g_el);
    cudaGetSymbolAddress((void**)&per, g_er);

    static int smem_set = 0;
    if (!smem_set) {
        cudaFuncSetAttribute(tfgemm, cudaFuncAttributeMaxDynamicSharedMemorySize, SMEM_GEMM);
        smem_set = 1;
    }

    const int TB = 256;
    long n_init = (long)N_NODES * DIN;
    k_init<<<(unsigned)((n_init + TB - 1) / TB), TB>>>(node_ids, entity_emb, basis_freq, phase, ts_ptr);

    const long n_edgehead = (long)R_TOTAL * N_EDGES * HEADS;
    const long n_zero     = (long)N_NODES * DIM_OUT;
    const long n_msgw     = (long)R_TOTAL * N_EDGES * 32;

    for (int l = 0; l < 2; l++) {
        k_zero<<<(unsigned)((n_zero + TB - 1) / TB), TB>>>();

        // z[r] = x @ fc_w[l][r] with fused el/er epilogue (tensor cores, tf32)
        dim3 gz(1, (N_NODES + 127) / 128, R_TOTAL);
        tfgemm<<<gz, 256, SMEM_GEMM>>>(px, 0,
                            fc_w + (long)l * R_TOTAL * DIN * DIM_OUT, (long)DIN * DIM_OUT,
                            pz, (long)N_NODES * DIM_OUT,
                            nullptr, N_NODES, DIM_OUT, DIN,
                            attn_l + (long)l * R_TOTAL * HEADS * DHEAD,
                            attn_r + (long)l * R_TOTAL * HEADS * DHEAD,
                            pel, per);

        k_edge_max<<<(unsigned)((n_edgehead + TB - 1) / TB), TB>>>(edge_src, edge_dst);
        k_edge_ex<<<(unsigned)((n_edgehead + TB - 1) / TB), TB>>>(edge_src, edge_dst);
        k_msg<<<(unsigned)((n_msgw + TB - 1) / TB), TB>>>(edge_src, edge_dst);

        k_finalize<<<(unsigned)((n_zero + TB - 1) / TB), TB>>>();
    }

    long n_bA = (long)2 * BATCH * KCLS;
    k_buildA<<<(unsigned)((n_bA + TB - 1) / TB), TB>>>(root_idx, rel, sub_rel_emb, obj_rel_emb);

    dim3 gc((NUME + 127) / 128, (BATCH + 127) / 128, 1);
    tfgemm<<<gc, 256, SMEM_GEMM>>>(pA, 0, sub_cls_w, 0, out, 0,
                        sub_cls_b, BATCH, NUME, KCLS,
                        nullptr, nullptr, nullptr, nullptr);
    tfgemm<<<gc, 256, SMEM_GEMM>>>(pA + (long)BATCH * KCLS, 0, obj_cls_w, 0,
                        out + (long)BATCH * NUME, 0,
                        obj_cls_b, BATCH, NUME, KCLS,
                        nullptr, nullptr, nullptr, nullptr);
    (void)in_sizes; (void)out_size;
}

// round 8
// speedup vs baseline: 2.9428x; 1.0304x over previous
#include <cuda_runtime.h>
#include <math.h>
#include <stdint.h>

#define NUME     30000
#define NUMR     8
#define DIM_IN   128
#define DIM_OUT  128
#define DIM_R    64
#define DIM_T    32
#define HEADS    4
#define DHEAD    32
#define R_TOTAL  17
#define N_NODES  20000
#define N_EDGES  15000
#define BATCH    1024
#define DIN      160
#define KCLS     (DIM_OUT + DIM_R)   // 192
#define NEG_SLOPE 0.2f

#define NSTAGE   3
#define A_STRIDE 24                            // floats per A smem row
#define B_STRIDE 132                           // floats per B smem row
#define STAGE_FLOATS (128 * A_STRIDE + 16 * B_STRIDE)   // 3072 + 2112 = 5184
#define SMEM_GEMM (NSTAGE * STAGE_FLOATS * 4)           // 62208 B

// k-permutation: rotate-left of 3-bit within-8 index (b2 b1 b0) -> (b1 b0 b2)
#define KPERM(k)  (((k) & ~7) | (((k) & 3) << 1) | (((k) >> 2) & 1))
#define KINV(k)   (((k) & ~7) | (((k) & 1) << 2) | (((k) >> 1) & 3))

// ---------------- scratch (device globals; no allocation allowed) ----------------
__device__ __align__(16) float    g_x[N_NODES * DIN];                         // tf32-rounded, k-permuted
__device__ __align__(16) float    g_z[(size_t)R_TOTAL * N_NODES * DIM_OUT];
__device__ __align__(16) float    g_el[R_TOTAL * N_NODES * HEADS];
__device__ __align__(16) float    g_er[R_TOTAL * N_NODES * HEADS];
__device__ __align__(16) unsigned g_menc[R_TOTAL * N_NODES * HEADS];
__device__ __align__(16) float    g_den[R_TOTAL * N_NODES * HEADS];
__device__ __align__(16) float    g_ex[R_TOTAL * N_EDGES * HEADS];
__device__ __align__(16) float    g_acc[N_NODES * DIM_OUT];
__device__ __align__(16) float    g_A[2 * BATCH * KCLS];                      // rounded, permuted
__device__ __align__(16) float    g_w[(size_t)2 * R_TOTAL * DIN * DIM_OUT];   // rounded, permuted fc_w
__device__ __align__(16) float    g_cw[(size_t)2 * KCLS * NUME];              // rounded, permuted cls W

__device__ __forceinline__ unsigned fenc(float f) {
    unsigned u = __float_as_uint(f);
    return (u & 0x80000000u) ? ~u : (u | 0x80000000u);
}
__device__ __forceinline__ float fdec(unsigned u) {
    return (u & 0x80000000u) ? __uint_as_float(u & 0x7FFFFFFFu) : __uint_as_float(~u);
}
__device__ __forceinline__ float tf32r(float f) {
    unsigned r;
    asm("cvt.rna.tf32.f32 %0, %1;" : "=r"(r) : "f"(f));
    return __uint_as_float(r);
}
__device__ __forceinline__ unsigned smem_u32(const void* p) {
    unsigned a;
    asm("{ .reg .u64 t; cvta.to.shared.u64 t, %1; cvt.u32.u64 %0, t; }" : "=r"(a) : "l"(p));
    return a;
}

// ---------------- prep kernels ----------------

__global__ void k_init(const int* __restrict__ node_ids,
                       const float* __restrict__ entity_emb,
                       const float* __restrict__ basis_freq,
                       const float* __restrict__ phase,
                       const int* __restrict__ ts_ptr) {
    long i = (long)blockIdx.x * blockDim.x + threadIdx.x;
    if (i >= (long)N_NODES * DIN) return;
    int n = (int)(i / DIN);
    int c = (int)(i % DIN);
    int nid = node_ids[n];
    float v;
    if (c < DIM_IN) {
        v = entity_emb[(long)(nid % NUME) * DIM_IN + c];
    } else {
        int ts = ts_ptr ? ts_ptr[0] : 31;
        float dt = (float)(ts - 1 - nid / NUME);
        int t = c - DIM_IN;
        v = cosf(dt * basis_freq[t] + phase[t]);
    }
    g_x[(long)n * DIN + KPERM(c)] = tf32r(v);
}

// fc_w [l*17+r][k][n] -> g_w rounded, k-permuted rows
__global__ void k_prep_w(const float* __restrict__ fc_w) {
    long i = (long)blockIdx.x * blockDim.x + threadIdx.x;
    if (i >= (long)2 * R_TOTAL * DIN * DIM_OUT) return;
    int n = (int)(i % DIM_OUT);
    int k = (int)((i / DIM_OUT) % DIN);
    long lr = i / ((long)DIM_OUT * DIN);
    g_w[(lr * DIN + KPERM(k)) * DIM_OUT + n] = tf32r(fc_w[i]);
}

// classifier weights [192][30000] -> g_cw rounded, permuted rows
__global__ void k_prep_cw(const float* __restrict__ sub_w, const float* __restrict__ obj_w) {
    long i = (long)blockIdx.x * blockDim.x + threadIdx.x;
    if (i >= (long)2 * KCLS * NUME) return;
    int n = (int)(i % NUME);
    int k = (int)((i / NUME) % KCLS);
    int z = (int)(i / ((long)KCLS * NUME));
    const float* W = z == 0 ? sub_w : obj_w;
    g_cw[((long)z * KCLS + KPERM(k)) * NUME + n] = tf32r(W[(long)k * NUME + n]);
}

__global__ void k_zero() {
    long i = (long)blockIdx.x * blockDim.x + threadIdx.x;
    const long NA = (long)R_TOTAL * N_NODES * HEADS;
    const long NB = (long)N_NODES * DIM_OUT;
    if (i < NA) { g_menc[i] = 0u; g_den[i] = 0.0f; }
    if (i < NB) { g_acc[i] = 0.0f; }
}

// ---------------- tf32 tensor-core GEMM, 3-stage cp.async, no in-loop CVT ----------------
// C[z] (M x N) = A[z] @ B[z] (+ bias_z). Inputs pre-rounded to tf32, k-permuted.
__global__ __launch_bounds__(256, 2) void tfgemm(
    const float* __restrict__ Aall, long sA,
    const float* __restrict__ Ball, long sB,
    float* __restrict__ Call, long sC,
    const float* __restrict__ bias0, const float* __restrict__ bias1,
    int M, int N, int K,
    const float* __restrict__ al, const float* __restrict__ ar,
    float* __restrict__ el, float* __restrict__ er) {
    extern __shared__ float smf[];
    const unsigned sbase = smem_u32(smf);
    const float* A = Aall + sA * blockIdx.z;
    const float* B = Ball + sB * blockIdx.z;
    float* C = Call + sC * blockIdx.z;
    const float* bias = (blockIdx.z == 0) ? bias0 : bias1;
    const int bm = blockIdx.y * 128;
    const int bn = blockIdx.x * 128;
    const int tid  = threadIdx.x;
    const int warp = tid >> 5;
    const int lane = tid & 31;
    const int wm = warp & 1;       // 2 warps along M (64 each)
    const int wn = warp >> 1;      // 4 warps along N (32 each)
    const int gid = lane >> 2;     // 0..7
    const int tig = lane & 3;      // 0..3
    const int nchunks = K >> 4;

    float acc[4][4][4];
#pragma unroll
    for (int i = 0; i < 4; i++)
#pragma unroll
        for (int j = 0; j < 4; j++)
#pragma unroll
            for (int q = 0; q < 4; q++) acc[i][j][q] = 0.0f;

    const int aq0 = tid, aq1 = tid + 256;
    const int arow0 = aq0 >> 2, ac0 = aq0 & 3;
    const int arow1 = aq1 >> 2, ac1 = aq1 & 3;
    const int brow0 = aq0 >> 5, bc0 = aq0 & 31;
    const int brow1 = aq1 >> 5, bc1 = aq1 & 31;

#define ISSUE_LOAD(chunk)                                                          \
    do {                                                                           \
        int _c = (chunk);                                                          \
        if (_c < nchunks) {                                                        \
            int _s = _c % NSTAGE;                                                  \
            unsigned _ab = sbase + (unsigned)(_s * STAGE_FLOATS) * 4u;             \
            unsigned _bb = _ab + 128u * A_STRIDE * 4u;                             \
            int _k0 = _c << 4;                                                     \
            {                                                                      \
                const float* _src = A + (long)(bm + arow0) * K + _k0 + ac0 * 4;    \
                unsigned _dst = _ab + (unsigned)(arow0 * A_STRIDE + ac0 * 4) * 4u; \
                unsigned _sz = (bm + arow0 < M) ? 16u : 0u;                        \
                asm volatile("cp.async.cg.shared.global [%0], [%1], 16, %2;"       \
                             :: "r"(_dst), "l"(_src), "r"(_sz));                   \
            }                                                                      \
            {                                                                      \
                const float* _src = A + (long)(bm + arow1) * K + _k0 + ac1 * 4;    \
                unsigned _dst = _ab + (unsigned)(arow1 * A_STRIDE + ac1 * 4) * 4u; \
                unsigned _sz = (bm + arow1 < M) ? 16u : 0u;                        \
                asm volatile("cp.async.cg.shared.global [%0], [%1], 16, %2;"       \
                             :: "r"(_dst), "l"(_src), "r"(_sz));                   \
            }                                                                      \
            {                                                                      \
                const float* _src = B + (long)(_k0 + brow0) * N + bn + bc0 * 4;    \
                unsigned _dst = _bb + (unsigned)(brow0 * B_STRIDE + bc0 * 4) * 4u; \
                unsigned _sz = (bn + bc0 * 4 + 3 < N) ? 16u : 0u;                  \
                asm volatile("cp.async.cg.shared.global [%0], [%1], 16, %2;"       \
                             :: "r"(_dst), "l"(_src), "r"(_sz));                   \
            }                                                                      \
            {                                                                      \
                const float* _src = B + (long)(_k0 + brow1) * N + bn + bc1 * 4;    \
                unsigned _dst = _bb + (unsigned)(brow1 * B_STRIDE + bc1 * 4) * 4u; \
                unsigned _sz = (bn + bc1 * 4 + 3 < N) ? 16u : 0u;                  \
                asm volatile("cp.async.cg.shared.global [%0], [%1], 16, %2;"       \
                             :: "r"(_dst), "l"(_src), "r"(_sz));                   \
            }                                                                      \
        }                                                                          \
        asm volatile("cp.async.commit_group;" ::: "memory");                       \
    } while (0)

    ISSUE_LOAD(0);
    ISSUE_LOAD(1);

    for (int c = 0; c < nchunks; c++) {
        asm volatile("cp.async.wait_group 1;" ::: "memory");
        __syncthreads();
        ISSUE_LOAD(c + 2);

        const float* Af = smf + (c % NSTAGE) * STAGE_FLOATS;
        const float* Bf = Af + 128 * A_STRIDE;
#pragma unroll
        for (int ks = 0; ks < 16; ks += 8) {
            unsigned af[4][4], bf[4][2];
            // permuted k: orig (tig, tig+4) live at phys (tig*2, tig*2+1)
#pragma unroll
            for (int mi = 0; mi < 4; mi++) {
                int mrow = wm * 64 + mi * 16 + gid;
                float2 p0 = *reinterpret_cast<const float2*>(&Af[mrow * A_STRIDE + ks + tig * 2]);
                float2 p1 = *reinterpret_cast<const float2*>(&Af[(mrow + 8) * A_STRIDE + ks + tig * 2]);
                af[mi][0] = __float_as_uint(p0.x);
                af[mi][2] = __float_as_uint(p0.y);
                af[mi][1] = __float_as_uint(p1.x);
                af[mi][3] = __float_as_uint(p1.y);
            }
#pragma unroll
            for (int nj = 0; nj < 4; nj++) {
                int ncol = wn * 32 + nj * 8 + gid;
                bf[nj][0] = __float_as_uint(Bf[(ks + tig * 2) * B_STRIDE + ncol]);
                bf[nj][1] = __float_as_uint(Bf[(ks + tig * 2 + 1) * B_STRIDE + ncol]);
            }
#pragma unroll
            for (int mi = 0; mi < 4; mi++)
#pragma unroll
                for (int nj = 0; nj < 4; nj++) {
                    asm volatile(
                        "mma.sync.aligned.m16n8k8.row.col.f32.tf32.tf32.f32 "
                        "{%0,%1,%2,%3}, {%4,%5,%6,%7}, {%8,%9}, {%0,%1,%2,%3};"
                        : "+f"(acc[mi][nj][0]), "+f"(acc[mi][nj][1]),
                          "+f"(acc[mi][nj][2]), "+f"(acc[mi][nj][3])
                        : "r"(af[mi][0]), "r"(af[mi][1]), "r"(af[mi][2]), "r"(af[mi][3]),
                          "r"(bf[nj][0]), "r"(bf[nj][1]));
                }
        }
    }

    // ---- epilogue: store C ----
#pragma unroll
    for (int mi = 0; mi < 4; mi++) {
        int m0 = bm + wm * 64 + mi * 16 + gid;
#pragma unroll
        for (int nj = 0; nj < 4; nj++) {
            int n0 = bn + wn * 32 + nj * 8 + tig * 2;
            if (n0 < N) {
                float b0 = bias ? bias[n0]     : 0.f;
                float b1 = bias ? bias[n0 + 1] : 0.f;
                if (m0 < M) {
                    C[(long)m0 * N + n0]     = acc[mi][nj][0] + b0;
                    C[(long)m0 * N + n0 + 1] = acc[mi][nj][1] + b1;
                }
                if (m0 + 8 < M) {
                    C[(long)(m0 + 8) * N + n0]     = acc[mi][nj][2] + b0;
                    C[(long)(m0 + 8) * N + n0 + 1] = acc[mi][nj][3] + b1;
                }
            }
        }
    }

    // ---- fused attention dots: el/er per (node, head=wn) ----
    if (al) {
        const float* alp = al + (long)blockIdx.z * HEADS * DHEAD + wn * DHEAD;
        const float* arp = ar + (long)blockIdx.z * HEADS * DHEAD + wn * DHEAD;
#pragma unroll
        for (int mi = 0; mi < 4; mi++) {
            float sl0 = 0.f, sr0 = 0.f, sl1 = 0.f, sr1 = 0.f;
#pragma unroll
            for (int nj = 0; nj < 4; nj++) {
                int dh = nj * 8 + tig * 2;
                float w0 = alp[dh], w1 = alp[dh + 1];
                float v0 = arp[dh], v1 = arp[dh + 1];
                sl0 += acc[mi][nj][0] * w0 + acc[mi][nj][1] * w1;
                sr0 += acc[mi][nj][0] * v0 + acc[mi][nj][1] * v1;
                sl1 += acc[mi][nj][2] * w0 + acc[mi][nj][3] * w1;
                sr1 += acc[mi][nj][2] * v0 + acc[mi][nj][3] * v1;
            }
#pragma unroll
            for (int o = 1; o <= 2; o <<= 1) {
                sl0 += __shfl_xor_sync(0xFFFFFFFFu, sl0, o);
                sr0 += __shfl_xor_sync(0xFFFFFFFFu, sr0, o);
                sl1 += __shfl_xor_sync(0xFFFFFFFFu, sl1, o);
                sr1 += __shfl_xor_sync(0xFFFFFFFFu, sr1, o);
            }
            if (tig == 0) {
                int m0 = bm + wm * 64 + mi * 16 + gid;
                long base = (long)blockIdx.z * N_NODES;
                if (m0 < M) {
                    el[(base + m0) * HEADS + wn] = sl0;
                    er[(base + m0) * HEADS + wn] = sr0;
                }
                if (m0 + 8 < M) {
                    el[(base + m0 + 8) * HEADS + wn] = sl1;
                    er[(base + m0 + 8) * HEADS + wn] = sr1;
                }
            }
        }
    }
}

// ---------------- edge kernels ----------------

__device__ __forceinline__ float edge_e(int r, int e, int h,
                                        const int* __restrict__ src,
                                        const int* __restrict__ dst,
                                        int* s_out, int* d_out_) {
    int s = src[r * N_EDGES + e];
    int d = dst[r * N_EDGES + e];
    *s_out = s; *d_out_ = d;
    float ev = g_el[((long)r * N_NODES + s) * HEADS + h] +
               g_er[((long)r * N_NODES + d) * HEADS + h];
    return (ev >= 0.f) ? ev : NEG_SLOPE * ev;
}

__global__ void k_edge_max(const int* __restrict__ src, const int* __restrict__ dst) {
    long i = (long)blockIdx.x * blockDim.x + threadIdx.x;
    if (i >= (long)R_TOTAL * N_EDGES * HEADS) return;
    int h = (int)(i % HEADS);
    int e = (int)((i / HEADS) % N_EDGES);
    int r = (int)(i / ((long)HEADS * N_EDGES));
    int s, d;
    float ev = edge_e(r, e, h, src, dst, &s, &d);
    atomicMax(&g_menc[((long)r * N_NODES + d) * HEADS + h], fenc(ev));
}

__global__ void k_edge_ex(const int* __restrict__ src, const int* __restrict__ dst) {
    long i = (long)blockIdx.x * blockDim.x + threadIdx.x;
    if (i >= (long)R_TOTAL * N_EDGES * HEADS) return;
    int h = (int)(i % HEADS);
    int e = (int)((i / HEADS) % N_EDGES);
    int r = (int)(i / ((long)HEADS * N_EDGES));
    int s, d;
    float ev = edge_e(r, e, h, src, dst, &s, &d);
    float m = fdec(g_menc[((long)r * N_NODES + d) * HEADS + h]);
    float ex = expf(ev - m);
    g_ex[i] = ex;
    atomicAdd(&g_den[((long)r * N_NODES + d) * HEADS + h], ex);
}

__global__ void k_msg(const int* __restrict__ src, const int* __restrict__ dst) {
    long gw = ((long)blockIdx.x * blockDim.x + threadIdx.x) >> 5;
    int lane = threadIdx.x & 31;
    if (gw >= (long)R_TOTAL * N_EDGES) return;
    int r = (int)(gw / N_EDGES);
    int e = (int)(gw % N_EDGES);
    int s = src[r * N_EDGES + e];
    int d = dst[r * N_EDGES + e];
    int c0 = lane * 4;
    int h = lane >> 3;
    float ex  = g_ex[gw * HEADS + h];
    float den = fmaxf(g_den[((long)r * N_NODES + d) * HEADS + h], 1e-9f);
    float a = ex / den;
    float4 zv = *reinterpret_cast<const float4*>(&g_z[((long)r * N_NODES + s) * DIM_OUT + c0]);
    float* p = &g_acc[(long)d * DIM_OUT + c0];
    asm volatile("red.global.add.v4.f32 [%0], {%1,%2,%3,%4};"
                 :: "l"(p), "f"(a * zv.x), "f"(a * zv.y), "f"(a * zv.z), "f"(a * zv.w)
                 : "memory");
}

// relu(mean) -> g_x (tf32-rounded, k-permuted)
__global__ void k_finalize() {
    long i = (long)blockIdx.x * blockDim.x + threadIdx.x;
    if (i >= (long)N_NODES * DIM_OUT) return;
    int n = (int)(i / DIM_OUT);
    int c = (int)(i % DIM_OUT);
    float v = g_acc[i] * (1.0f / (float)R_TOTAL);
    v = (v > 0.f) ? v : 0.f;
    g_x[(long)n * DIN + KPERM(c)] = tf32r(v);
}

// classifier A matrices (rounded, permuted): thread owns PHYS output column p
__global__ void k_buildA(const int* __restrict__ root_idx,
                         const int* __restrict__ rel,
                         const float* __restrict__ sub_rel_emb,
                         const float* __restrict__ obj_rel_emb) {
    long i = (long)blockIdx.x * blockDim.x + threadIdx.x;
    if (i >= (long)2 * BATCH * KCLS) return;
    int p = (int)(i % KCLS);
    int row = (int)(i / KCLS);
    int z = row >> 10;          // 0 = sub_pred inputs, 1 = obj_pred inputs
    int b = row & 1023;
    float v;
    if (p < DIM_OUT) {
        // g_x is already rounded+permuted: phys-to-phys copy preserves mapping
        int node = root_idx[z == 0 ? BATCH + b : b];
        v = g_x[(long)node * DIN + p];
    } else {
        int d = KINV(p - DIM_OUT);
        const float* re = (z == 0) ? obj_rel_emb : sub_rel_emb;
        v = tf32r(re[rel[b] * DIM_R + d]);
    }
    g_A[i] = v;
}

// ---------------- launch ----------------
extern "C" void kernel_launch(void* const* d_in, const int* in_sizes, int n_in,
                              void* d_out, int out_size) {
    const int*   node_ids    = (const int*)d_in[0];
    const int*   edge_src    = (const int*)d_in[1];
    const int*   edge_dst    = (const int*)d_in[2];
    const int*   root_idx    = (const int*)d_in[3];
    const int*   rel         = (const int*)d_in[4];
    const float* entity_emb  = (const float*)d_in[5];
    const float* basis_freq  = (const float*)d_in[6];
    const float* phase       = (const float*)d_in[7];
    const float* fc_w        = (const float*)d_in[8];
    const float* attn_l      = (const float*)d_in[9];
    const float* attn_r      = (const float*)d_in[10];
    const float* sub_rel_emb = (const float*)d_in[11];
    const float* obj_rel_emb = (const float*)d_in[12];
    const float* sub_cls_w   = (const float*)d_in[13];
    const float* sub_cls_b   = (const float*)d_in[14];
    const float* obj_cls_w   = (const float*)d_in[15];
    const float* obj_cls_b   = (const float*)d_in[16];
    const int*   ts_ptr      = (n_in > 17) ? (const int*)d_in[17] : nullptr;

    float* out = (float*)d_out;

    float *px, *pz, *pA, *pel, *per, *pw, *pcw;
    cudaGetSymbolAddress((void**)&px, g_x);
    cudaGetSymbolAddress((void**)&pz, g_z);
    cudaGetSymbolAddress((void**)&pA, g_A);
    cudaGetSymbolAddress((void**)&pel, g_el);
    cudaGetSymbolAddress((void**)&per, g_er);
    cudaGetSymbolAddress((void**)&pw, g_w);
    cudaGetSymbolAddress((void**)&pcw, g_cw);

    static int smem_set = 0;
    if (!smem_set) {
        cudaFuncSetAttribute(tfgemm, cudaFuncAttributeMaxDynamicSharedMemorySize, SMEM_GEMM);
        smem_set = 1;
    }

    const int TB = 256;
    long n_init = (long)N_NODES * DIN;
    k_init<<<(unsigned)((n_init + TB - 1) / TB), TB>>>(node_ids, entity_emb, basis_freq, phase, ts_ptr);
    long n_pw = (long)2 * R_TOTAL * DIN * DIM_OUT;
    k_prep_w<<<(unsigned)((n_pw + TB - 1) / TB), TB>>>(fc_w);
    long n_pcw = (long)2 * KCLS * NUME;
    k_prep_cw<<<(unsigned)((n_pcw + TB - 1) / TB), TB>>>(sub_cls_w, obj_cls_w);

    const long n_edgehead = (long)R_TOTAL * N_EDGES * HEADS;
    const long n_zero     = (long)N_NODES * DIM_OUT;
    const long n_msgw     = (long)R_TOTAL * N_EDGES * 32;

    for (int l = 0; l < 2; l++) {
        k_zero<<<(unsigned)((n_zero + TB - 1) / TB), TB>>>();

        dim3 gz(1, (N_NODES + 127) / 128, R_TOTAL);
        tfgemm<<<gz, 256, SMEM_GEMM>>>(px, 0,
                            pw + (long)l * R_TOTAL * DIN * DIM_OUT, (long)DIN * DIM_OUT,
                            pz, (long)N_NODES * DIM_OUT,
                            nullptr, nullptr, N_NODES, DIM_OUT, DIN,
                            attn_l + (long)l * R_TOTAL * HEADS * DHEAD,
                            attn_r + (long)l * R_TOTAL * HEADS * DHEAD,
                            pel, per);

        k_edge_max<<<(unsigned)((n_edgehead + TB - 1) / TB), TB>>>(edge_src, edge_dst);
        k_edge_ex<<<(unsigned)((n_edgehead + TB - 1) / TB), TB>>>(edge_src, edge_dst);
        k_msg<<<(unsigned)((n_msgw + TB - 1) / TB), TB>>>(edge_src, edge_dst);

        k_finalize<<<(unsigned)((n_zero + TB - 1) / TB), TB>>>();
    }

    long n_bA = (long)2 * BATCH * KCLS;
    k_buildA<<<(unsigned)((n_bA + TB - 1) / TB), TB>>>(root_idx, rel, sub_rel_emb, obj_rel_emb);

    // both classifier GEMMs in one launch (z = 0: sub, 1: obj)
    dim3 gc((NUME + 127) / 128, (BATCH + 127) / 128, 2);
    tfgemm<<<gc, 256, SMEM_GEMM>>>(pA, (long)BATCH * KCLS,
                        pcw, (long)KCLS * NUME,
                        out, (long)BATCH * NUME,
                        sub_cls_b, obj_cls_b, BATCH, NUME, KCLS,
                        nullptr, nullptr, nullptr, nullptr);
    (void)in_sizes; (void)out_size;
}

// round 9
// speedup vs baseline: 3.3621x; 1.1425x over previous
#include <cuda_runtime.h>
#include <cuda_fp16.h>
#include <math.h>
#include <stdint.h>

#define NUME     30000
#define NUMR     8
#define DIM_IN   128
#define DIM_OUT  128
#define DIM_R    64
#define DIM_T    32
#define HEADS    4
#define DHEAD    32
#define R_TOTAL  17
#define N_NODES  20000
#define N_EDGES  15000
#define BATCH    1024
#define DIN      160
#define KCLS     (DIM_OUT + DIM_R)   // 192
#define NEG_SLOPE 0.2f
#define NPAD     30080

#define NSTAGE   3
#define AS       20                              // b32 per smem row (16 data + 4 pad)
#define STAGE_B32 (256 * AS)                     // A tile (128 rows) + B tile (128 rows)
#define SMEM_GEMM (NSTAGE * STAGE_B32 * 4)       // 61440 B

// ---------------- scratch (device globals; no allocation allowed) ----------------
__device__ __align__(16) __half   g_x[(size_t)N_NODES * DIN];                  // [node][k] fp16
__device__ __align__(16) float    g_z[(size_t)R_TOTAL * N_NODES * DIM_OUT];
__device__ __align__(16) float    g_el[R_TOTAL * N_NODES * HEADS];
__device__ __align__(16) float    g_er[R_TOTAL * N_NODES * HEADS];
__device__ __align__(16) unsigned g_menc[R_TOTAL * N_NODES * HEADS];
__device__ __align__(16) float    g_den[R_TOTAL * N_NODES * HEADS];
__device__ __align__(16) float    g_ex[R_TOTAL * N_EDGES * HEADS];
__device__ __align__(16) float    g_acc[N_NODES * DIM_OUT];
__device__ __align__(16) __half   g_A[2 * BATCH * KCLS];                       // [row][k] fp16
__device__ __align__(16) __half   g_w[(size_t)2 * R_TOTAL * DIM_OUT * DIN];   // [lr][n][k] fp16 (transposed)
__device__ __align__(16) __half   g_cw[(size_t)2 * NPAD * KCLS];              // [z][n][k] fp16 (transposed)

__device__ __forceinline__ unsigned fenc(float f) {
    unsigned u = __float_as_uint(f);
    return (u & 0x80000000u) ? ~u : (u | 0x80000000u);
}
__device__ __forceinline__ float fdec(unsigned u) {
    return (u & 0x80000000u) ? __uint_as_float(u & 0x7FFFFFFFu) : __uint_as_float(~u);
}
__device__ __forceinline__ unsigned smem_u32(const void* p) {
    unsigned a;
    asm("{ .reg .u64 t; cvta.to.shared.u64 t, %1; cvt.u32.u64 %0, t; }" : "=r"(a) : "l"(p));
    return a;
}

// ---------------- prep kernels ----------------

// builds x (fp16) AND zeroes layer-0 softmax/accumulator state
__global__ void k_init(const int* __restrict__ node_ids,
                       const float* __restrict__ entity_emb,
                       const float* __restrict__ basis_freq,
                       const float* __restrict__ phase,
                       const int* __restrict__ ts_ptr) {
    long i = (long)blockIdx.x * blockDim.x + threadIdx.x;
    const long NA = (long)R_TOTAL * N_NODES * HEADS;
    const long NB = (long)N_NODES * DIM_OUT;
    if (i < NA) { g_menc[i] = 0u; g_den[i] = 0.0f; }
    if (i < NB) { g_acc[i] = 0.0f; }
    if (i >= (long)N_NODES * DIN) return;
    int n = (int)(i / DIN);
    int c = (int)(i % DIN);
    int nid = node_ids[n];
    float v;
    if (c < DIM_IN) {
        v = entity_emb[(long)(nid % NUME) * DIM_IN + c];
    } else {
        int ts = ts_ptr ? ts_ptr[0] : 31;
        float dt = (float)(ts - 1 - nid / NUME);
        int t = c - DIM_IN;
        v = cosf(dt * basis_freq[t] + phase[t]);
    }
    g_x[i] = __float2half_rn(v);
}

// fc_w [lr][k][n] -> g_w [lr][n][k] fp16
__global__ void k_prep_w(const float* __restrict__ fc_w) {
    long i = (long)blockIdx.x * blockDim.x + threadIdx.x;
    if (i >= (long)2 * R_TOTAL * DIN * DIM_OUT) return;
    int n = (int)(i % DIM_OUT);
    int k = (int)((i / DIM_OUT) % DIN);
    long lr = i / ((long)DIM_OUT * DIN);
    g_w[(lr * DIM_OUT + n) * DIN + k] = __float2half_rn(fc_w[i]);
}

// classifier W [192][30000] -> g_cw [z][n][k] fp16, tiled transpose
__global__ void k_prep_cw(const float* __restrict__ sub_w, const float* __restrict__ obj_w) {
    __shared__ float tile[32][33];
    int z = blockIdx.z;
    const float* W = z == 0 ? sub_w : obj_w;
    int bn = blockIdx.x * 32;
    int bk = blockIdx.y * 32;
    int tx = threadIdx.x, ty = threadIdx.y;   // (32, 8)
#pragma unroll
    for (int j = 0; j < 4; j++) {
        int k = bk + ty + 8 * j;
        int n = bn + tx;
        tile[ty + 8 * j][tx] = (n < NUME) ? W[(long)k * NUME + n] : 0.f;
    }
    __syncthreads();
#pragma unroll
    for (int j = 0; j < 4; j++) {
        int n = bn + ty + 8 * j;
        int k = bk + tx;
        if (n < NUME)
            g_cw[((long)z * NPAD + n) * KCLS + k] = __float2half_rn(tile[tx][ty + 8 * j]);
    }
}

// ---------------- fp16 tensor-core GEMM, 3-stage cp.async ----------------
// C[z] (M x N) = A[z] (M x K fp16 row-major) @ B[z] (N x K fp16, i.e. B^T) (+ bias_z)
// If al != nullptr: fused el/er epilogue (requires N == 128, bn == 0).
// K % 32 == 0.
__global__ __launch_bounds__(256, 2) void hgemm(
    const __half* __restrict__ Aall, long sA,
    const __half* __restrict__ Ball, long sB,
    float* __restrict__ Call, long sC,
    const float* __restrict__ bias0, const float* __restrict__ bias1,
    int M, int N, int K,
    const float* __restrict__ al, const float* __restrict__ ar,
    float* __restrict__ el, float* __restrict__ er) {
    extern __shared__ uint32_t smu[];
    const unsigned sbase = smem_u32(smu);
    const __half* A = Aall + sA * blockIdx.z;
    const __half* B = Ball + sB * blockIdx.z;
    float* C = Call + sC * blockIdx.z;
    const float* bias = (blockIdx.z == 0) ? bias0 : bias1;
    const int bm = blockIdx.y * 128;
    const int bn = blockIdx.x * 128;
    const int tid  = threadIdx.x;
    const int warp = tid >> 5;
    const int lane = tid & 31;
    const int wm = warp & 1;       // 2 warps along M (64 each)
    const int wn = warp >> 1;      // 4 warps along N (32 each)
    const int gid = lane >> 2;     // 0..7
    const int tig = lane & 3;      // 0..3
    const int nchunks = K >> 5;    // 32 fp16 per chunk

    float acc[4][4][4];
#pragma unroll
    for (int i = 0; i < 4; i++)
#pragma unroll
        for (int j = 0; j < 4; j++)
#pragma unroll
            for (int q = 0; q < 4; q++) acc[i][j][q] = 0.0f;

    // load mapping: per tile 128 rows x 64 B = 512 x 16B chunks; 2 per thread
    const int r0 = tid >> 2, c0 = tid & 3;
    const int r1 = (tid + 256) >> 2, c1 = tid & 3;

#define ISSUE_LOAD(chunk)                                                            \
    do {                                                                             \
        int _c = (chunk);                                                            \
        if (_c < nchunks) {                                                          \
            int _s = _c % NSTAGE;                                                    \
            unsigned _ab = sbase + (unsigned)(_s * STAGE_B32) * 4u;                  \
            unsigned _bb = _ab + 128u * AS * 4u;                                     \
            int _k0 = _c << 5;                                                       \
            {                                                                        \
                const __half* _src = A + (long)(bm + r0) * K + _k0 + c0 * 8;         \
                unsigned _sz = (bm + r0 < M) ? 16u : 0u;                             \
                asm volatile("cp.async.cg.shared.global [%0], [%1], 16, %2;"         \
                             :: "r"(_ab + (unsigned)(r0 * AS + c0 * 4) * 4u),        \
                                "l"(_src), "r"(_sz));                                \
            }                                                                        \
            {                                                                        \
                const __half* _src = A + (long)(bm + r1) * K + _k0 + c1 * 8;         \
                unsigned _sz = (bm + r1 < M) ? 16u : 0u;                             \
                asm volatile("cp.async.cg.shared.global [%0], [%1], 16, %2;"         \
                             :: "r"(_ab + (unsigned)(r1 * AS + c1 * 4) * 4u),        \
                                "l"(_src), "r"(_sz));                                \
            }                                                                        \
            {                                                                        \
                const __half* _src = B + (long)(bn + r0) * K + _k0 + c0 * 8;         \
                unsigned _sz = (bn + r0 < N) ? 16u : 0u;                             \
                asm volatile("cp.async.cg.shared.global [%0], [%1], 16, %2;"         \
                             :: "r"(_bb + (unsigned)(r0 * AS + c0 * 4) * 4u),        \
                                "l"(_src), "r"(_sz));                                \
            }                                                                        \
            {                                                                        \
                const __half* _src = B + (long)(bn + r1) * K + _k0 + c1 * 8;         \
                unsigned _sz = (bn + r1 < N) ? 16u : 0u;                             \
                asm volatile("cp.async.cg.shared.global [%0], [%1], 16, %2;"         \
                             :: "r"(_bb + (unsigned)(r1 * AS + c1 * 4) * 4u),        \
                                "l"(_src), "r"(_sz));                                \
            }                                                                        \
        }                                                                            \
        asm volatile("cp.async.commit_group;" ::: "memory");                         \
    } while (0)

    ISSUE_LOAD(0);
    ISSUE_LOAD(1);

    for (int c = 0; c < nchunks; c++) {
        asm volatile("cp.async.wait_group 1;" ::: "memory");
        __syncthreads();
        ISSUE_LOAD(c + 2);

        const uint32_t* Af = smu + (c % NSTAGE) * STAGE_B32;
        const uint32_t* Bf = Af + 128 * AS;
#pragma unroll
        for (int ks = 0; ks < 2; ks++) {
            const int kc = ks * 8;
            uint32_t af[4][4], bf[4][2];
#pragma unroll
            for (int mi = 0; mi < 4; mi++) {
                int mrow = wm * 64 + mi * 16 + gid;
                af[mi][0] = Af[mrow * AS + kc + tig];
                af[mi][1] = Af[(mrow + 8) * AS + kc + tig];
                af[mi][2] = Af[mrow * AS + kc + tig + 4];
                af[mi][3] = Af[(mrow + 8) * AS + kc + tig + 4];
            }
#pragma unroll
            for (int nj = 0; nj < 4; nj++) {
                int ncol = wn * 32 + nj * 8 + gid;
                bf[nj][0] = Bf[ncol * AS + kc + tig];
                bf[nj][1] = Bf[ncol * AS + kc + tig + 4];
            }
#pragma unroll
            for (int mi = 0; mi < 4; mi++)
#pragma unroll
                for (int nj = 0; nj < 4; nj++) {
                    asm volatile(
                        "mma.sync.aligned.m16n8k16.row.col.f32.f16.f16.f32 "
                        "{%0,%1,%2,%3}, {%4,%5,%6,%7}, {%8,%9}, {%0,%1,%2,%3};"
                        : "+f"(acc[mi][nj][0]), "+f"(acc[mi][nj][1]),
                          "+f"(acc[mi][nj][2]), "+f"(acc[mi][nj][3])
                        : "r"(af[mi][0]), "r"(af[mi][1]), "r"(af[mi][2]), "r"(af[mi][3]),
                          "r"(bf[nj][0]), "r"(bf[nj][1]));
                }
        }
    }

    // ---- epilogue: store C ----
#pragma unroll
    for (int mi = 0; mi < 4; mi++) {
        int m0 = bm + wm * 64 + mi * 16 + gid;
#pragma unroll
        for (int nj = 0; nj < 4; nj++) {
            int n0 = bn + wn * 32 + nj * 8 + tig * 2;
            if (n0 < N) {
                float b0 = bias ? bias[n0]     : 0.f;
                float b1 = bias ? bias[n0 + 1] : 0.f;
                if (m0 < M) {
                    C[(long)m0 * N + n0]     = acc[mi][nj][0] + b0;
                    C[(long)m0 * N + n0 + 1] = acc[mi][nj][1] + b1;
                }
                if (m0 + 8 < M) {
                    C[(long)(m0 + 8) * N + n0]     = acc[mi][nj][2] + b0;
                    C[(long)(m0 + 8) * N + n0 + 1] = acc[mi][nj][3] + b1;
                }
            }
        }
    }

    // ---- fused attention dots: el/er per (node, head=wn) ----
    if (al) {
        const float* alp = al + (long)blockIdx.z * HEADS * DHEAD + wn * DHEAD;
        const float* arp = ar + (long)blockIdx.z * HEADS * DHEAD + wn * DHEAD;
#pragma unroll
        for (int mi = 0; mi < 4; mi++) {
            float sl0 = 0.f, sr0 = 0.f, sl1 = 0.f, sr1 = 0.f;
#pragma unroll
            for (int nj = 0; nj < 4; nj++) {
                int dh = nj * 8 + tig * 2;
                float w0 = alp[dh], w1 = alp[dh + 1];
                float v0 = arp[dh], v1 = arp[dh + 1];
                sl0 += acc[mi][nj][0] * w0 + acc[mi][nj][1] * w1;
                sr0 += acc[mi][nj][0] * v0 + acc[mi][nj][1] * v1;
                sl1 += acc[mi][nj][2] * w0 + acc[mi][nj][3] * w1;
                sr1 += acc[mi][nj][2] * v0 + acc[mi][nj][3] * v1;
            }
#pragma unroll
            for (int o = 1; o <= 2; o <<= 1) {
                sl0 += __shfl_xor_sync(0xFFFFFFFFu, sl0, o);
                sr0 += __shfl_xor_sync(0xFFFFFFFFu, sr0, o);
                sl1 += __shfl_xor_sync(0xFFFFFFFFu, sl1, o);
                sr1 += __shfl_xor_sync(0xFFFFFFFFu, sr1, o);
            }
            if (tig == 0) {
                int m0 = bm + wm * 64 + mi * 16 + gid;
                long base = (long)blockIdx.z * N_NODES;
                if (m0 < M) {
                    el[(base + m0) * HEADS + wn] = sl0;
                    er[(base + m0) * HEADS + wn] = sr0;
                }
                if (m0 + 8 < M) {
                    el[(base + m0 + 8) * HEADS + wn] = sl1;
                    er[(base + m0 + 8) * HEADS + wn] = sr1;
                }
            }
        }
    }
}

// ---------------- edge kernels ----------------

__device__ __forceinline__ float edge_e(int r, int e, int h,
                                        const int* __restrict__ src,
                                        const int* __restrict__ dst,
                                        int* s_out, int* d_out_) {
    int s = src[r * N_EDGES + e];
    int d = dst[r * N_EDGES + e];
    *s_out = s; *d_out_ = d;
    float ev = g_el[((long)r * N_NODES + s) * HEADS + h] +
               g_er[((long)r * N_NODES + d) * HEADS + h];
    return (ev >= 0.f) ? ev : NEG_SLOPE * ev;
}

__global__ void k_edge_max(const int* __restrict__ src, const int* __restrict__ dst) {
    long i = (long)blockIdx.x * blockDim.x + threadIdx.x;
    if (i >= (long)R_TOTAL * N_EDGES * HEADS) return;
    int h = (int)(i % HEADS);
    int e = (int)((i / HEADS) % N_EDGES);
    int r = (int)(i / ((long)HEADS * N_EDGES));
    int s, d;
    float ev = edge_e(r, e, h, src, dst, &s, &d);
    atomicMax(&g_menc[((long)r * N_NODES + d) * HEADS + h], fenc(ev));
}

__global__ void k_edge_ex(const int* __restrict__ src, const int* __restrict__ dst) {
    long i = (long)blockIdx.x * blockDim.x + threadIdx.x;
    if (i >= (long)R_TOTAL * N_EDGES * HEADS) return;
    int h = (int)(i % HEADS);
    int e = (int)((i / HEADS) % N_EDGES);
    int r = (int)(i / ((long)HEADS * N_EDGES));
    int s, d;
    float ev = edge_e(r, e, h, src, dst, &s, &d);
    float m = fdec(g_menc[((long)r * N_NODES + d) * HEADS + h]);
    float ex = expf(ev - m);
    g_ex[i] = ex;
    atomicAdd(&g_den[((long)r * N_NODES + d) * HEADS + h], ex);
}

__global__ void k_msg(const int* __restrict__ src, const int* __restrict__ dst) {
    long gw = ((long)blockIdx.x * blockDim.x + threadIdx.x) >> 5;
    int lane = threadIdx.x & 31;
    if (gw >= (long)R_TOTAL * N_EDGES) return;
    int r = (int)(gw / N_EDGES);
    int e = (int)(gw % N_EDGES);
    int s = src[r * N_EDGES + e];
    int d = dst[r * N_EDGES + e];
    int c0 = lane * 4;
    int h = lane >> 3;
    float ex  = g_ex[gw * HEADS + h];
    float den = fmaxf(g_den[((long)r * N_NODES + d) * HEADS + h], 1e-9f);
    float a = ex / den;
    float4 zv = *reinterpret_cast<const float4*>(&g_z[((long)r * N_NODES + s) * DIM_OUT + c0]);
    float* p = &g_acc[(long)d * DIM_OUT + c0];
    asm volatile("red.global.add.v4.f32 [%0], {%1,%2,%3,%4};"
                 :: "l"(p), "f"(a * zv.x), "f"(a * zv.y), "f"(a * zv.z), "f"(a * zv.w)
                 : "memory");
}

// relu(mean) -> g_x fp16; ALSO zeroes state for the next layer
__global__ void k_finalize() {
    long i = (long)blockIdx.x * blockDim.x + threadIdx.x;
    const long NA = (long)R_TOTAL * N_NODES * HEADS;
    if (i < NA) { g_menc[i] = 0u; g_den[i] = 0.0f; }
    if (i >= (long)N_NODES * DIM_OUT) return;
    int n = (int)(i / DIM_OUT);
    int c = (int)(i % DIM_OUT);
    float v = g_acc[i] * (1.0f / (float)R_TOTAL);
    g_acc[i] = 0.0f;
    v = (v > 0.f) ? v : 0.f;
    g_x[(long)n * DIN + c] = __float2half_rn(v);
}

// classifier A matrices (fp16): row layout [k]
__global__ void k_buildA(const int* __restrict__ root_idx,
                         const int* __restrict__ rel,
                         const float* __restrict__ sub_rel_emb,
                         const float* __restrict__ obj_rel_emb) {
    long i = (long)blockIdx.x * blockDim.x + threadIdx.x;
    if (i >= (long)2 * BATCH * KCLS) return;
    int k = (int)(i % KCLS);
    int row = (int)(i / KCLS);
    int z = row >> 10;          // 0 = sub_pred inputs, 1 = obj_pred inputs
    int b = row & 1023;
    __half v;
    if (k < DIM_OUT) {
        int node = root_idx[z == 0 ? BATCH + b : b];
        v = g_x[(long)node * DIN + k];
    } else {
        const float* re = (z == 0) ? obj_rel_emb : sub_rel_emb;
        v = __float2half_rn(re[rel[b] * DIM_R + (k - DIM_OUT)]);
    }
    g_A[i] = v;
}

// ---------------- launch ----------------
extern "C" void kernel_launch(void* const* d_in, const int* in_sizes, int n_in,
                              void* d_out, int out_size) {
    const int*   node_ids    = (const int*)d_in[0];
    const int*   edge_src    = (const int*)d_in[1];
    const int*   edge_dst    = (const int*)d_in[2];
    const int*   root_idx    = (const int*)d_in[3];
    const int*   rel         = (const int*)d_in[4];
    const float* entity_emb  = (const float*)d_in[5];
    const float* basis_freq  = (const float*)d_in[6];
    const float* phase       = (const float*)d_in[7];
    const float* fc_w        = (const float*)d_in[8];
    const float* attn_l      = (const float*)d_in[9];
    const float* attn_r      = (const float*)d_in[10];
    const float* sub_rel_emb = (const float*)d_in[11];
    const float* obj_rel_emb = (const float*)d_in[12];
    const float* sub_cls_w   = (const float*)d_in[13];
    const float* sub_cls_b   = (const float*)d_in[14];
    const float* obj_cls_w   = (const float*)d_in[15];
    const float* obj_cls_b   = (const float*)d_in[16];
    const int*   ts_ptr      = (n_in > 17) ? (const int*)d_in[17] : nullptr;

    float* out = (float*)d_out;

    __half *px, *pA, *pw, *pcw;
    float *pz, *pel, *per;
    cudaGetSymbolAddress((void**)&px, g_x);
    cudaGetSymbolAddress((void**)&pz, g_z);
    cudaGetSymbolAddress((void**)&pA, g_A);
    cudaGetSymbolAddress((void**)&pel, g_el);
    cudaGetSymbolAddress((void**)&per, g_er);
    cudaGetSymbolAddress((void**)&pw, g_w);
    cudaGetSymbolAddress((void**)&pcw, g_cw);

    static int smem_set = 0;
    if (!smem_set) {
        cudaFuncSetAttribute(hgemm, cudaFuncAttributeMaxDynamicSharedMemorySize, SMEM_GEMM);
        smem_set = 1;
    }

    const int TB = 256;
    long n_init = (long)N_NODES * DIN;
    k_init<<<(unsigned)((n_init + TB - 1) / TB), TB>>>(node_ids, entity_emb, basis_freq, phase, ts_ptr);
    long n_pw = (long)2 * R_TOTAL * DIN * DIM_OUT;
    k_prep_w<<<(unsigned)((n_pw + TB - 1) / TB), TB>>>(fc_w);
    dim3 gcw(NPAD / 32, KCLS / 32, 2);
    k_prep_cw<<<gcw, dim3(32, 8)>>>(sub_cls_w, obj_cls_w);

    const long n_edgehead = (long)R_TOTAL * N_EDGES * HEADS;
    const long n_zero     = (long)N_NODES * DIM_OUT;
    const long n_msgw     = (long)R_TOTAL * N_EDGES * 32;

    for (int l = 0; l < 2; l++) {
        // z[r] = x @ W[l][r]^T with fused el/er (fp16 tensor cores); K=160 -> 5 chunks
        dim3 gz(1, (N_NODES + 127) / 128, R_TOTAL);
        hgemm<<<gz, 256, SMEM_GEMM>>>(px, 0,
                            pw + (long)l * R_TOTAL * DIM_OUT * DIN, (long)DIM_OUT * DIN,
                            pz, (long)N_NODES * DIM_OUT,
                            nullptr, nullptr, N_NODES, DIM_OUT, DIN,
                            attn_l + (long)l * R_TOTAL * HEADS * DHEAD,
                            attn_r + (long)l * R_TOTAL * HEADS * DHEAD,
                            pel, per);

        k_edge_max<<<(unsigned)((n_edgehead + TB - 1) / TB), TB>>>(edge_src, edge_dst);
        k_edge_ex<<<(unsigned)((n_edgehead + TB - 1) / TB), TB>>>(edge_src, edge_dst);
        k_msg<<<(unsigned)((n_msgw + TB - 1) / TB), TB>>>(edge_src, edge_dst);

        k_finalize<<<(unsigned)((n_zero + TB - 1) / TB), TB>>>();
    }

    long n_bA = (long)2 * BATCH * KCLS;
    k_buildA<<<(unsigned)((n_bA + TB - 1) / TB), TB>>>(root_idx, rel, sub_rel_emb, obj_rel_emb);

    // both classifier GEMMs in one launch (z = 0: sub, 1: obj); K=192 -> 6 chunks
    dim3 gc(NPAD / 128, BATCH / 128, 2);
    hgemm<<<gc, 256, SMEM_GEMM>>>(pA, (long)BATCH * KCLS,
                        pcw, (long)NPAD * KCLS,
                        out, (long)BATCH * NUME,
                        sub_cls_b, obj_cls_b, BATCH, NUME, KCLS,
                        nullptr, nullptr, nullptr, nullptr);
    (void)in_sizes; (void)out_size;
}

// round 10
// speedup vs baseline: 3.4634x; 1.0301x over previous
#include <cuda_runtime.h>
#include <cuda_fp16.h>
#include <math.h>
#include <stdint.h>

#define NUME     30000
#define NUMR     8
#define DIM_IN   128
#define DIM_OUT  128
#define DIM_R    64
#define DIM_T    32
#define HEADS    4
#define DHEAD    32
#define R_TOTAL  17
#define N_NODES  20000
#define N_EDGES  15000
#define BATCH    1024
#define DIN      160
#define KCLS     (DIM_OUT + DIM_R)   // 192
#define NEG_SLOPE 0.2f
#define NPAD     30080

#define NSTAGE   3
#define AS       20                              // b32 per smem row (16 data + 4 pad)
#define STAGE_B32 (256 * AS)                     // A tile (128 rows) + B tile (128 rows)
#define SMEM_GEMM (NSTAGE * STAGE_B32 * 4)       // 61440 B

// ---------------- scratch (device globals; no allocation allowed) ----------------
__device__ __align__(16) __half   g_x[(size_t)N_NODES * DIN];                  // [node][k] fp16
__device__ __align__(16) float    g_z[(size_t)R_TOTAL * N_NODES * DIM_OUT];
__device__ __align__(16) float    g_el[R_TOTAL * N_NODES * HEADS];
__device__ __align__(16) float    g_er[R_TOTAL * N_NODES * HEADS];
__device__ __align__(16) unsigned g_menc[R_TOTAL * N_NODES * HEADS];
__device__ __align__(16) float    g_den[R_TOTAL * N_NODES * HEADS];
__device__ __align__(16) float    g_ex[R_TOTAL * N_EDGES * HEADS];
__device__ __align__(16) float    g_acc[N_NODES * DIM_OUT];
__device__ __align__(16) __half   g_A[2 * BATCH * KCLS];                       // [row][k] fp16
__device__ __align__(16) __half   g_w[(size_t)2 * R_TOTAL * DIM_OUT * DIN];   // [lr][n][k] fp16 (transposed)
__device__ __align__(16) __half   g_cw[(size_t)2 * NPAD * KCLS];              // [z][n][k] fp16 (transposed)

__device__ __forceinline__ unsigned fenc(float f) {
    unsigned u = __float_as_uint(f);
    return (u & 0x80000000u) ? ~u : (u | 0x80000000u);
}
__device__ __forceinline__ float fdec(unsigned u) {
    return (u & 0x80000000u) ? __uint_as_float(u & 0x7FFFFFFFu) : __uint_as_float(~u);
}
__device__ __forceinline__ unsigned smem_u32(const void* p) {
    unsigned a;
    asm("{ .reg .u64 t; cvta.to.shared.u64 t, %1; cvt.u32.u64 %0, t; }" : "=r"(a) : "l"(p));
    return a;
}
__device__ __forceinline__ void ldsm4(uint32_t& r0, uint32_t& r1, uint32_t& r2, uint32_t& r3,
                                      unsigned addr) {
    asm volatile("ldmatrix.sync.aligned.m8n8.x4.shared.b16 {%0,%1,%2,%3}, [%4];"
                 : "=r"(r0), "=r"(r1), "=r"(r2), "=r"(r3) : "r"(addr));
}

// ---------------- prep kernels ----------------

// builds x (fp16) AND zeroes layer-0 softmax/accumulator state
__global__ void k_init(const int* __restrict__ node_ids,
                       const float* __restrict__ entity_emb,
                       const float* __restrict__ basis_freq,
                       const float* __restrict__ phase,
                       const int* __restrict__ ts_ptr) {
    long i = (long)blockIdx.x * blockDim.x + threadIdx.x;
    const long NA = (long)R_TOTAL * N_NODES * HEADS;
    const long NB = (long)N_NODES * DIM_OUT;
    if (i < NA) { g_menc[i] = 0u; g_den[i] = 0.0f; }
    if (i < NB) { g_acc[i] = 0.0f; }
    if (i >= (long)N_NODES * DIN) return;
    int n = (int)(i / DIN);
    int c = (int)(i % DIN);
    int nid = node_ids[n];
    float v;
    if (c < DIM_IN) {
        v = entity_emb[(long)(nid % NUME) * DIM_IN + c];
    } else {
        int ts = ts_ptr ? ts_ptr[0] : 31;
        float dt = (float)(ts - 1 - nid / NUME);
        int t = c - DIM_IN;
        v = cosf(dt * basis_freq[t] + phase[t]);
    }
    g_x[i] = __float2half_rn(v);
}

// fc_w [lr][k][n] -> g_w [lr][n][k] fp16
__global__ void k_prep_w(const float* __restrict__ fc_w) {
    long i = (long)blockIdx.x * blockDim.x + threadIdx.x;
    if (i >= (long)2 * R_TOTAL * DIN * DIM_OUT) return;
    int n = (int)(i % DIM_OUT);
    int k = (int)((i / DIM_OUT) % DIN);
    long lr = i / ((long)DIM_OUT * DIN);
    g_w[(lr * DIM_OUT + n) * DIN + k] = __float2half_rn(fc_w[i]);
}

// classifier W [192][30000] -> g_cw [z][n][k] fp16, tiled transpose
__global__ void k_prep_cw(const float* __restrict__ sub_w, const float* __restrict__ obj_w) {
    __shared__ float tile[32][33];
    int z = blockIdx.z;
    const float* W = z == 0 ? sub_w : obj_w;
    int bn = blockIdx.x * 32;
    int bk = blockIdx.y * 32;
    int tx = threadIdx.x, ty = threadIdx.y;   // (32, 8)
#pragma unroll
    for (int j = 0; j < 4; j++) {
        int k = bk + ty + 8 * j;
        int n = bn + tx;
        tile[ty + 8 * j][tx] = (n < NUME) ? W[(long)k * NUME + n] : 0.f;
    }
    __syncthreads();
#pragma unroll
    for (int j = 0; j < 4; j++) {
        int n = bn + ty + 8 * j;
        int k = bk + tx;
        if (n < NUME)
            g_cw[((long)z * NPAD + n) * KCLS + k] = __float2half_rn(tile[tx][ty + 8 * j]);
    }
}

// ---------------- fp16 tensor-core GEMM, 3-stage cp.async + ldmatrix ----------------
// C[z] (M x N) = A[z] (M x K fp16 row-major) @ B[z] (N x K fp16, i.e. B^T) (+ bias_z)
// If al != nullptr: fused el/er epilogue (requires N == 128, bn == 0).
// K % 32 == 0.
__global__ __launch_bounds__(256, 2) void hgemm(
    const __half* __restrict__ Aall, long sA,
    const __half* __restrict__ Ball, long sB,
    float* __restrict__ Call, long sC,
    const float* __restrict__ bias0, const float* __restrict__ bias1,
    int M, int N, int K,
    const float* __restrict__ al, const float* __restrict__ ar,
    float* __restrict__ el, float* __restrict__ er) {
    extern __shared__ uint32_t smu[];
    const unsigned sbase = smem_u32(smu);
    const __half* A = Aall + sA * blockIdx.z;
    const __half* B = Ball + sB * blockIdx.z;
    float* C = Call + sC * blockIdx.z;
    const float* bias = (blockIdx.z == 0) ? bias0 : bias1;
    const int bm = blockIdx.y * 128;
    const int bn = blockIdx.x * 128;
    const int tid  = threadIdx.x;
    const int warp = tid >> 5;
    const int lane = tid & 31;
    const int wm = warp & 1;       // 2 warps along M (64 each)
    const int wn = warp >> 1;      // 4 warps along N (32 each)
    const int gid = lane >> 2;     // 0..7
    const int tig = lane & 3;      // 0..3
    const int nchunks = K >> 5;    // 32 fp16 per chunk

    // ldmatrix per-lane byte offsets within a tile (row stride 80B)
    // A groups: g0 rows+0 k+0, g1 rows+8 k+0, g2 rows+0 k+16B, g3 rows+8 k+16B
    const unsigned aoff = (unsigned)(((lane & 7) + ((lane >> 3) & 1) * 8) * 80 + (lane >> 4) * 16);
    // B groups: g0 rows+0 k+0, g1 rows+0 k+16B, g2 rows+8 k+0, g3 rows+8 k+16B
    const unsigned boff = (unsigned)(((lane & 7) + ((lane >> 4) & 1) * 8) * 80 + ((lane >> 3) & 1) * 16);

    float acc[4][4][4];
#pragma unroll
    for (int i = 0; i < 4; i++)
#pragma unroll
        for (int j = 0; j < 4; j++)
#pragma unroll
            for (int q = 0; q < 4; q++) acc[i][j][q] = 0.0f;

    // load mapping: per tile 128 rows x 64 B = 512 x 16B chunks; 2 per thread
    const int r0 = tid >> 2, c0 = tid & 3;
    const int r1 = (tid + 256) >> 2, c1 = tid & 3;

#define ISSUE_LOAD(chunk)                                                            \
    do {                                                                             \
        int _c = (chunk);                                                            \
        if (_c < nchunks) {                                                          \
            int _s = _c % NSTAGE;                                                    \
            unsigned _ab = sbase + (unsigned)(_s * STAGE_B32) * 4u;                  \
            unsigned _bb = _ab + 128u * AS * 4u;                                     \
            int _k0 = _c << 5;                                                       \
            {                                                                        \
                const __half* _src = A + (long)(bm + r0) * K + _k0 + c0 * 8;         \
                unsigned _sz = (bm + r0 < M) ? 16u : 0u;                             \
                asm volatile("cp.async.cg.shared.global [%0], [%1], 16, %2;"         \
                             :: "r"(_ab + (unsigned)(r0 * AS + c0 * 4) * 4u),        \
                                "l"(_src), "r"(_sz));                                \
            }                                                                        \
            {                                                                        \
                const __half* _src = A + (long)(bm + r1) * K + _k0 + c1 * 8;         \
                unsigned _sz = (bm + r1 < M) ? 16u : 0u;                             \
                asm volatile("cp.async.cg.shared.global [%0], [%1], 16, %2;"         \
                             :: "r"(_ab + (unsigned)(r1 * AS + c1 * 4) * 4u),        \
                                "l"(_src), "r"(_sz));                                \
            }                                                                        \
            {                                                                        \
                const __half* _src = B + (long)(bn + r0) * K + _k0 + c0 * 8;         \
                unsigned _sz = (bn + r0 < N) ? 16u : 0u;                             \
                asm volatile("cp.async.cg.shared.global [%0], [%1], 16, %2;"         \
                             :: "r"(_bb + (unsigned)(r0 * AS + c0 * 4) * 4u),        \
                                "l"(_src), "r"(_sz));                                \
            }                                                                        \
            {                                                                        \
                const __half* _src = B + (long)(bn + r1) * K + _k0 + c1 * 8;         \
                unsigned _sz = (bn + r1 < N) ? 16u : 0u;                             \
                asm volatile("cp.async.cg.shared.global [%0], [%1], 16, %2;"         \
                             :: "r"(_bb + (unsigned)(r1 * AS + c1 * 4) * 4u),        \
                                "l"(_src), "r"(_sz));                                \
            }                                                                        \
        }                                                                            \
        asm volatile("cp.async.commit_group;" ::: "memory");                         \
    } while (0)

    ISSUE_LOAD(0);
    ISSUE_LOAD(1);

    for (int c = 0; c < nchunks; c++) {
        asm volatile("cp.async.wait_group 1;" ::: "memory");
        __syncthreads();
        ISSUE_LOAD(c + 2);

        const unsigned stA = sbase + (unsigned)((c % NSTAGE) * STAGE_B32) * 4u;
        const unsigned stB = stA + 128u * AS * 4u;
#pragma unroll
        for (int ks = 0; ks < 2; ks++) {
            const unsigned kb = (unsigned)(ks * 32);   // byte offset of this k16 within row
            uint32_t af[4][4], bf[4][2];
#pragma unroll
            for (int mi = 0; mi < 4; mi++) {
                unsigned base = stA + (unsigned)((wm * 64 + mi * 16) * 80) + kb + aoff;
                ldsm4(af[mi][0], af[mi][1], af[mi][2], af[mi][3], base);
            }
            ldsm4(bf[0][0], bf[0][1], bf[1][0], bf[1][1],
                  stB + (unsigned)((wn * 32) * 80) + kb + boff);
            ldsm4(bf[2][0], bf[2][1], bf[3][0], bf[3][1],
                  stB + (unsigned)((wn * 32 + 16) * 80) + kb + boff);
#pragma unroll
            for (int mi = 0; mi < 4; mi++)
#pragma unroll
                for (int nj = 0; nj < 4; nj++) {
                    asm volatile(
                        "mma.sync.aligned.m16n8k16.row.col.f32.f16.f16.f32 "
                        "{%0,%1,%2,%3}, {%4,%5,%6,%7}, {%8,%9}, {%0,%1,%2,%3};"
                        : "+f"(acc[mi][nj][0]), "+f"(acc[mi][nj][1]),
                          "+f"(acc[mi][nj][2]), "+f"(acc[mi][nj][3])
                        : "r"(af[mi][0]), "r"(af[mi][1]), "r"(af[mi][2]), "r"(af[mi][3]),
                          "r"(bf[nj][0]), "r"(bf[nj][1]));
                }
        }
    }

    // ---- epilogue: store C ----
#pragma unroll
    for (int mi = 0; mi < 4; mi++) {
        int m0 = bm + wm * 64 + mi * 16 + gid;
#pragma unroll
        for (int nj = 0; nj < 4; nj++) {
            int n0 = bn + wn * 32 + nj * 8 + tig * 2;
            if (n0 < N) {
                float b0 = bias ? bias[n0]     : 0.f;
                float b1 = bias ? bias[n0 + 1] : 0.f;
                if (m0 < M) {
                    C[(long)m0 * N + n0]     = acc[mi][nj][0] + b0;
                    C[(long)m0 * N + n0 + 1] = acc[mi][nj][1] + b1;
                }
                if (m0 + 8 < M) {
                    C[(long)(m0 + 8) * N + n0]     = acc[mi][nj][2] + b0;
                    C[(long)(m0 + 8) * N + n0 + 1] = acc[mi][nj][3] + b1;
                }
            }
        }
    }

    // ---- fused attention dots: el/er per (node, head=wn) ----
    if (al) {
        const float* alp = al + (long)blockIdx.z * HEADS * DHEAD + wn * DHEAD;
        const float* arp = ar + (long)blockIdx.z * HEADS * DHEAD + wn * DHEAD;
#pragma unroll
        for (int mi = 0; mi < 4; mi++) {
            float sl0 = 0.f, sr0 = 0.f, sl1 = 0.f, sr1 = 0.f;
#pragma unroll
            for (int nj = 0; nj < 4; nj++) {
                int dh = nj * 8 + tig * 2;
                float w0 = alp[dh], w1 = alp[dh + 1];
                float v0 = arp[dh], v1 = arp[dh + 1];
                sl0 += acc[mi][nj][0] * w0 + acc[mi][nj][1] * w1;
                sr0 += acc[mi][nj][0] * v0 + acc[mi][nj][1] * v1;
                sl1 += acc[mi][nj][2] * w0 + acc[mi][nj][3] * w1;
                sr1 += acc[mi][nj][2] * v0 + acc[mi][nj][3] * v1;
            }
#pragma unroll
            for (int o = 1; o <= 2; o <<= 1) {
                sl0 += __shfl_xor_sync(0xFFFFFFFFu, sl0, o);
                sr0 += __shfl_xor_sync(0xFFFFFFFFu, sr0, o);
                sl1 += __shfl_xor_sync(0xFFFFFFFFu, sl1, o);
                sr1 += __shfl_xor_sync(0xFFFFFFFFu, sr1, o);
            }
            if (tig == 0) {
                int m0 = bm + wm * 64 + mi * 16 + gid;
                long base = (long)blockIdx.z * N_NODES;
                if (m0 < M) {
                    el[(base + m0) * HEADS + wn] = sl0;
                    er[(base + m0) * HEADS + wn] = sr0;
                }
                if (m0 + 8 < M) {
                    el[(base + m0 + 8) * HEADS + wn] = sl1;
                    er[(base + m0 + 8) * HEADS + wn] = sr1;
                }
            }
        }
    }
}

// ---------------- edge kernels ----------------

__device__ __forceinline__ float edge_e(int r, int e, int h,
                                        const int* __restrict__ src,
                                        const int* __restrict__ dst,
                                        int* s_out, int* d_out_) {
    int s = src[r * N_EDGES + e];
    int d = dst[r * N_EDGES + e];
    *s_out = s; *d_out_ = d;
    float ev = g_el[((long)r * N_NODES + s) * HEADS + h] +
               g_er[((long)r * N_NODES + d) * HEADS + h];
    return (ev >= 0.f) ? ev : NEG_SLOPE * ev;
}

__global__ void k_edge_max(const int* __restrict__ src, const int* __restrict__ dst) {
    long i = (long)blockIdx.x * blockDim.x + threadIdx.x;
    if (i >= (long)R_TOTAL * N_EDGES * HEADS) return;
    int h = (int)(i % HEADS);
    int e = (int)((i / HEADS) % N_EDGES);
    int r = (int)(i / ((long)HEADS * N_EDGES));
    int s, d;
    float ev = edge_e(r, e, h, src, dst, &s, &d);
    atomicMax(&g_menc[((long)r * N_NODES + d) * HEADS + h], fenc(ev));
}

__global__ void k_edge_ex(const int* __restrict__ src, const int* __restrict__ dst) {
    long i = (long)blockIdx.x * blockDim.x + threadIdx.x;
    if (i >= (long)R_TOTAL * N_EDGES * HEADS) return;
    int h = (int)(i % HEADS);
    int e = (int)((i / HEADS) % N_EDGES);
    int r = (int)(i / ((long)HEADS * N_EDGES));
    int s, d;
    float ev = edge_e(r, e, h, src, dst, &s, &d);
    float m = fdec(g_menc[((long)r * N_NODES + d) * HEADS + h]);
    float ex = expf(ev - m);
    g_ex[i] = ex;
    atomicAdd(&g_den[((long)r * N_NODES + d) * HEADS + h], ex);
}

__global__ void k_msg(const int* __restrict__ src, const int* __restrict__ dst) {
    long gw = ((long)blockIdx.x * blockDim.x + threadIdx.x) >> 5;
    int lane = threadIdx.x & 31;
    if (gw >= (long)R_TOTAL * N_EDGES) return;
    int r = (int)(gw / N_EDGES);
    int e = (int)(gw % N_EDGES);
    int s = src[r * N_EDGES + e];
    int d = dst[r * N_EDGES + e];
    int c0 = lane * 4;
    int h = lane >> 3;
    float ex  = g_ex[gw * HEADS + h];
    float den = fmaxf(g_den[((long)r * N_NODES + d) * HEADS + h], 1e-9f);
    float a = ex / den;
    float4 zv = *reinterpret_cast<const float4*>(&g_z[((long)r * N_NODES + s) * DIM_OUT + c0]);
    float* p = &g_acc[(long)d * DIM_OUT + c0];
    asm volatile("red.global.add.v4.f32 [%0], {%1,%2,%3,%4};"
                 :: "l"(p), "f"(a * zv.x), "f"(a * zv.y), "f"(a * zv.z), "f"(a * zv.w)
                 : "memory");
}

// relu(mean) -> g_x fp16; ALSO zeroes state for the next layer
__global__ void k_finalize() {
    long i = (long)blockIdx.x * blockDim.x + threadIdx.x;
    const long NA = (long)R_TOTAL * N_NODES * HEADS;
    if (i < NA) { g_menc[i] = 0u; g_den[i] = 0.0f; }
    if (i >= (long)N_NODES * DIM_OUT) return;
    int n = (int)(i / DIM_OUT);
    int c = (int)(i % DIM_OUT);
    float v = g_acc[i] * (1.0f / (float)R_TOTAL);
    g_acc[i] = 0.0f;
    v = (v > 0.f) ? v : 0.f;
    g_x[(long)n * DIN + c] = __float2half_rn(v);
}

// classifier A matrices (fp16): row layout [k]
__global__ void k_buildA(const int* __restrict__ root_idx,
                         const int* __restrict__ rel,
                         const float* __restrict__ sub_rel_emb,
                         const float* __restrict__ obj_rel_emb) {
    long i = (long)blockIdx.x * blockDim.x + threadIdx.x;
    if (i >= (long)2 * BATCH * KCLS) return;
    int k = (int)(i % KCLS);
    int row = (int)(i / KCLS);
    int z = row >> 10;          // 0 = sub_pred inputs, 1 = obj_pred inputs
    int b = row & 1023;
    __half v;
    if (k < DIM_OUT) {
        int node = root_idx[z == 0 ? BATCH + b : b];
        v = g_x[(long)node * DIN + k];
    } else {
        const float* re = (z == 0) ? obj_rel_emb : sub_rel_emb;
        v = __float2half_rn(re[rel[b] * DIM_R + (k - DIM_OUT)]);
    }
    g_A[i] = v;
}

// ---------------- launch ----------------
extern "C" void kernel_launch(void* const* d_in, const int* in_sizes, int n_in,
                              void* d_out, int out_size) {
    const int*   node_ids    = (const int*)d_in[0];
    const int*   edge_src    = (const int*)d_in[1];
    const int*   edge_dst    = (const int*)d_in[2];
    const int*   root_idx    = (const int*)d_in[3];
    const int*   rel         = (const int*)d_in[4];
    const float* entity_emb  = (const float*)d_in[5];
    const float* basis_freq  = (const float*)d_in[6];
    const float* phase       = (const float*)d_in[7];
    const float* fc_w        = (const float*)d_in[8];
    const float* attn_l      = (const float*)d_in[9];
    const float* attn_r      = (const float*)d_in[10];
    const float* sub_rel_emb = (const float*)d_in[11];
    const float* obj_rel_emb = (const float*)d_in[12];
    const float* sub_cls_w   = (const float*)d_in[13];
    const float* sub_cls_b   = (const float*)d_in[14];
    const float* obj_cls_w   = (const float*)d_in[15];
    const float* obj_cls_b   = (const float*)d_in[16];
    const int*   ts_ptr      = (n_in > 17) ? (const int*)d_in[17] : nullptr;

    float* out = (float*)d_out;

    __half *px, *pA, *pw, *pcw;
    float *pz, *pel, *per;
    cudaGetSymbolAddress((void**)&px, g_x);
    cudaGetSymbolAddress((void**)&pz, g_z);
    cudaGetSymbolAddress((void**)&pA, g_A);
    cudaGetSymbolAddress((void**)&pel, g_el);
    cudaGetSymbolAddress((void**)&per, g_er);
    cudaGetSymbolAddress((void**)&pw, g_w);
    cudaGetSymbolAddress((void**)&pcw, g_cw);

    static int smem_set = 0;
    if (!smem_set) {
        cudaFuncSetAttribute(hgemm, cudaFuncAttributeMaxDynamicSharedMemorySize, SMEM_GEMM);
        smem_set = 1;
    }

    const int TB = 256;
    long n_init = (long)N_NODES * DIN;
    k_init<<<(unsigned)((n_init + TB - 1) / TB), TB>>>(node_ids, entity_emb, basis_freq, phase, ts_ptr);
    long n_pw = (long)2 * R_TOTAL * DIN * DIM_OUT;
    k_prep_w<<<(unsigned)((n_pw + TB - 1) / TB), TB>>>(fc_w);
    dim3 gcw(NPAD / 32, KCLS / 32, 2);
    k_prep_cw<<<gcw, dim3(32, 8)>>>(sub_cls_w, obj_cls_w);

    const long n_edgehead = (long)R_TOTAL * N_EDGES * HEADS;
    const long n_zero     = (long)N_NODES * DIM_OUT;
    const long n_msgw     = (long)R_TOTAL * N_EDGES * 32;

    for (int l = 0; l < 2; l++) {
        // z[r] = x @ W[l][r]^T with fused el/er (fp16 tensor cores); K=160 -> 5 chunks
        dim3 gz(1, (N_NODES + 127) / 128, R_TOTAL);
        hgemm<<<gz, 256, SMEM_GEMM>>>(px, 0,
                            pw + (long)l * R_TOTAL * DIM_OUT * DIN, (long)DIM_OUT * DIN,
                            pz, (long)N_NODES * DIM_OUT,
                            nullptr, nullptr, N_NODES, DIM_OUT, DIN,
                            attn_l + (long)l * R_TOTAL * HEADS * DHEAD,
                            attn_r + (long)l * R_TOTAL * HEADS * DHEAD,
                            pel, per);

        k_edge_max<<<(unsigned)((n_edgehead + TB - 1) / TB), TB>>>(edge_src, edge_dst);
        k_edge_ex<<<(unsigned)((n_edgehead + TB - 1) / TB), TB>>>(edge_src, edge_dst);
        k_msg<<<(unsigned)((n_msgw + TB - 1) / TB), TB>>>(edge_src, edge_dst);

        k_finalize<<<(unsigned)((n_zero + TB - 1) / TB), TB>>>();
    }

    long n_bA = (long)2 * BATCH * KCLS;
    k_buildA<<<(unsigned)((n_bA + TB - 1) / TB), TB>>>(root_idx, rel, sub_rel_emb, obj_rel_emb);

    // both classifier GEMMs in one launch (z = 0: sub, 1: obj); K=192 -> 6 chunks
    dim3 gc(NPAD / 128, BATCH / 128, 2);
    hgemm<<<gc, 256, SMEM_GEMM>>>(pA, (long)BATCH * KCLS,
                        pcw, (long)NPAD * KCLS,
                        out, (long)BATCH * NUME,
                        sub_cls_b, obj_cls_b, BATCH, NUME, KCLS,
                        nullptr, nullptr, nullptr, nullptr);
    (void)in_sizes; (void)out_size;
}